// round 11
// baseline (speedup 1.0000x reference)
#include <cuda_runtime.h>
#include <cuda_bf16.h>
#include <cstdint>

#define B_ 4
#define C_ 64
#define N_ 6400
#define LOG2E 1.4426950408889634f

// ---------------- device-global scratch -------------------------------------
__device__ __align__(16) __nv_bfloat16 g_q_h[B_*N_*C_];   // [B][N][C] (theta, pre-scaled by log2e)
__device__ __align__(16) __nv_bfloat16 g_q_l[B_*N_*C_];
__device__ __align__(16) __nv_bfloat16 g_k_h[B_*N_*C_];   // [B][N][C]
__device__ __align__(16) __nv_bfloat16 g_k_l[B_*N_*C_];
__device__ __align__(16) __nv_bfloat16 g_v_h[B_*C_*N_];   // [B][C][N]
__device__ __align__(16) __nv_bfloat16 g_v_l[B_*C_*N_];
__device__ __align__(16) float g_p0[B_*C_*N_];            // split-0 partial O (unnormalized)
__device__ __align__(16) float g_p1[B_*C_*N_];            // split-1 partial O
__device__ float g_l0[B_*N_];                              // split-0 partial row sums
__device__ float g_l1[B_*N_];
__device__ float g_Wy  [B_*C_*N_];
__device__ float g_stats[2*C_];

// ---------------- helpers ----------------------------------------------------
__device__ __forceinline__ uint32_t smem_u32(const void* p) {
    uint32_t a;
    asm("{ .reg .u64 t; cvta.to.shared.u64 t, %1; cvt.u32.u64 %0, t; }" : "=r"(a) : "l"(p));
    return a;
}
__device__ __forceinline__ void cpa16(uint32_t dst, const void* src) {
    asm volatile("cp.async.cg.shared.global [%0], [%1], 16;" :: "r"(dst), "l"(src));
}
__device__ __forceinline__ void mma_bf16(float* d, const uint32_t* a, const uint32_t* b) {
    asm volatile("mma.sync.aligned.m16n8k16.row.col.f32.bf16.bf16.f32 "
        "{%0,%1,%2,%3}, {%4,%5,%6,%7}, {%8,%9}, {%0,%1,%2,%3};"
        : "+f"(d[0]), "+f"(d[1]), "+f"(d[2]), "+f"(d[3])
        : "r"(a[0]), "r"(a[1]), "r"(a[2]), "r"(a[3]), "r"(b[0]), "r"(b[1]));
}
__device__ __forceinline__ void ldmx4(uint32_t* r, uint32_t a) {
    asm volatile("ldmatrix.sync.aligned.m8n8.x4.shared.b16 {%0,%1,%2,%3}, [%4];"
        : "=r"(r[0]), "=r"(r[1]), "=r"(r[2]), "=r"(r[3]) : "r"(a));
}
__device__ __forceinline__ float ex2(float x) {
    float r;
    asm("ex2.approx.f32 %0, %1;" : "=f"(r) : "f"(x));
    return r;
}
// pack (a,b) -> bf16x2 hi-plane + residual lo-plane (lo 16 bits = a)
__device__ __forceinline__ void split2(float a, float b, uint32_t& hi, uint32_t& lo) {
    uint32_t h;
    asm("cvt.rn.bf16x2.f32 %0, %1, %2;" : "=r"(h) : "f"(b), "f"(a));
    float ah = __uint_as_float(h << 16);
    float bh = __uint_as_float(h & 0xffff0000u);
    float al = a - ah, bl = b - bh;
    uint32_t l;
    asm("cvt.rn.bf16x2.f32 %0, %1, %2;" : "=r"(l) : "f"(bl), "f"(al));
    hi = h; lo = l;
}
__device__ __forceinline__ uint32_t pack_bf16x2(float a, float b) {
    uint32_t h;
    asm("cvt.rn.bf16x2.f32 %0, %1, %2;" : "=r"(h) : "f"(b), "f"(a));
    return h;
}

// ---------------- kernel 1: projections -> bf16 hi/lo planes ----------------
__global__ __launch_bounds__(256) void proj3_kernel(
    const float* __restrict__ x,
    const float* __restrict__ wt, const float* __restrict__ bt,
    const float* __restrict__ wp, const float* __restrict__ bp,
    const float* __restrict__ wg, const float* __restrict__ bg)
{
    __shared__ __align__(16) float xs[64*68];
    __shared__ __align__(16) float ws[64*68];
    const int b  = blockIdx.y;
    const int n0 = blockIdx.x * 64;
    const int t  = threadIdx.x;
    const int tx = t & 15, ty = t >> 4;

    if (blockIdx.x == 0 && b == 0 && t < 128) g_stats[t] = 0.f;

    for (int i = t; i < 4096; i += 256) {
        int c = i >> 6, n = i & 63;
        xs[c*68 + n] = x[((size_t)b*64 + c)*6400 + n0 + n];
    }
    const float* W[3]  = {wt, wp, wg};
    const float* BV[3] = {bt, bp, bg};

    for (int m = 0; m < 3; m++) {
        __syncthreads();
        for (int i = t; i < 4096; i += 256) ws[(i & 63)*68 + (i >> 6)] = W[m][i];
        __syncthreads();

        float acc[4][4];
        #pragma unroll
        for (int j = 0; j < 4; j++) {
            float bb = BV[m][4*tx + j];
            #pragma unroll
            for (int r = 0; r < 4; r++) acc[r][j] = bb;
        }
        #pragma unroll 4
        for (int c = 0; c < 64; c++) {
            float4 a  = *(const float4*)&xs[c*68 + 4*ty];
            float4 w4 = *(const float4*)&ws[c*68 + 4*tx];
            acc[0][0] += a.x*w4.x; acc[0][1] += a.x*w4.y; acc[0][2] += a.x*w4.z; acc[0][3] += a.x*w4.w;
            acc[1][0] += a.y*w4.x; acc[1][1] += a.y*w4.y; acc[1][2] += a.y*w4.z; acc[1][3] += a.y*w4.w;
            acc[2][0] += a.z*w4.x; acc[2][1] += a.z*w4.y; acc[2][2] += a.z*w4.z; acc[2][3] += a.z*w4.w;
            acc[3][0] += a.w*w4.x; acc[3][1] += a.w*w4.y; acc[3][2] += a.w*w4.z; acc[3][3] += a.w*w4.w;
        }
        if (m == 0) {    // theta: pre-scale by log2(e) so softmax uses ex2 directly
            #pragma unroll
            for (int r = 0; r < 4; r++)
                #pragma unroll
                for (int j = 0; j < 4; j++) acc[r][j] *= LOG2E;
        }
        if (m < 2) {
            __nv_bfloat16* ph = (m == 0) ? g_q_h : g_k_h;
            __nv_bfloat16* pl = (m == 0) ? g_q_l : g_k_l;
            #pragma unroll
            for (int r = 0; r < 4; r++) {
                uint32_t h01, l01, h23, l23;
                split2(acc[r][0], acc[r][1], h01, l01);
                split2(acc[r][2], acc[r][3], h23, l23);
                size_t idx = ((size_t)b*6400 + n0 + 4*ty + r)*64 + 4*tx;
                *(uint2*)&ph[idx] = make_uint2(h01, h23);
                *(uint2*)&pl[idx] = make_uint2(l01, l23);
            }
        } else {
            #pragma unroll
            for (int j = 0; j < 4; j++) {
                uint32_t hA, lA, hB, lB;
                split2(acc[0][j], acc[1][j], hA, lA);
                split2(acc[2][j], acc[3][j], hB, lB);
                size_t idx = ((size_t)b*64 + 4*tx + j)*6400 + n0 + 4*ty;
                *(uint2*)&g_v_h[idx] = make_uint2(hA, hB);
                *(uint2*)&g_v_l[idx] = make_uint2(lA, lB);
            }
        }
    }
}

// ---------------- kernel 2: flash attention, split-K, K ping-pong -----------
// smem: bufA (Q then K-odd) 0..16K, bufB (K-even) 16K..32K, V 32K..48K
// each 16K region = hi plane (8K) + lo plane (8K); 64 rows x 128B, XOR swizzle
#define KB0  0u
#define KB1  16384u
#define PV0  32768u
#define NCHUNK 50                  // 50 key-chunks of 64 per split

__device__ __forceinline__ void ld_plane(uint32_t dst, const __nv_bfloat16* src,
                                         int rowstride, int t)
{
    #pragma unroll
    for (int k = 0; k < 4; k++) {
        int idx = t + k*128;               // 512 chunks total
        int row = idx >> 3, ch = idx & 7;
        cpa16(dst + (uint32_t)row*128u + (uint32_t)((ch ^ (row & 7))*16),
              src + (size_t)row*rowstride + ch*8);
    }
}

__global__ __launch_bounds__(128, 4) void flash_kernel()
{
    __shared__ __align__(128) char smem[49152];
    const uint32_t sb = smem_u32(smem);
    const int t    = threadIdx.x;
    const int lane = t & 31;
    const int wid  = t >> 5;
    const int b    = blockIdx.y;
    const int n0   = blockIdx.x * 64;
    const int sp   = blockIdx.z;          // key-range split: 0 or 1
    const int kbase = sp * 3200;
    const int m0   = wid * 16;

    // prologue: group0 = {Q->bufB(KB1), K0->bufA(KB0)}, group1 = {V0}
    ld_plane(sb + KB1,         g_q_h + ((size_t)b*6400 + n0)*64, 64, t);
    ld_plane(sb + KB1 + 8192u, g_q_l + ((size_t)b*6400 + n0)*64, 64, t);
    ld_plane(sb + KB0,         g_k_h + ((size_t)b*6400 + kbase)*64, 64, t);
    ld_plane(sb + KB0 + 8192u, g_k_l + ((size_t)b*6400 + kbase)*64, 64, t);
    asm volatile("cp.async.commit_group;" ::: "memory");
    ld_plane(sb + PV0,         g_v_h + (size_t)b*64*6400 + kbase, 6400, t);
    ld_plane(sb + PV0 + 8192u, g_v_l + (size_t)b*64*6400 + kbase, 6400, t);
    asm volatile("cp.async.commit_group;" ::: "memory");

    // lane-derived ldmatrix address components
    const uint32_t ar   = (uint32_t)(lane & 7) + ((uint32_t)((lane >> 3) & 1) << 3);
    const uint32_t ax   = (uint32_t)((lane >> 4) & 1);
    const uint32_t axr  = (uint32_t)(lane & 7);
    const uint32_t br   = (uint32_t)(lane & 7);
    const uint32_t bx   = (uint32_t)((lane >> 3) & 1);
    const uint32_t bpl  = ((uint32_t)(lane >> 4) & 1) * 8192u;  // lanes 16-31 -> lo plane

    uint32_t qh[4][4], ql[4][4];
    float O[8][4];
    #pragma unroll
    for (int i = 0; i < 8; i++)
        #pragma unroll
        for (int j = 0; j < 4; j++) O[i][j] = 0.f;
    float lsA = 0.f, lsB = 0.f;

    #pragma unroll 1
    for (int i = 0; i < NCHUNK; i++) {
        const uint32_t kbuf = sb + ((i & 1) ? KB1 : KB0);

        // K(i) [and Q at i=0] ready; leave V(i) pending
        asm volatile("cp.async.wait_group 1;" ::: "memory");
        __syncthreads();

        if (i == 0) {
            #pragma unroll
            for (int kb = 0; kb < 4; kb++) {
                uint32_t R  = (uint32_t)m0 + ar;
                uint32_t ch = ((uint32_t)(kb*2) + ax) ^ axr;
                ldmx4(qh[kb], sb + KB1 + R*128u + ch*16u);
                ldmx4(ql[kb], sb + KB1 + 8192u + R*128u + ch*16u);
            }
            __syncthreads();          // Q buffer free before K(1) prefetch
        }
        // prefetch K(i+1) into the other buffer NOW (it was freed a chunk ago)
        if (i < NCHUNK-1) {
            uint32_t nbuf = sb + (((i + 1) & 1) ? KB1 : KB0);
            ld_plane(nbuf,         g_k_h + ((size_t)b*6400 + kbase + (i+1)*64)*64, 64, t);
            ld_plane(nbuf + 8192u, g_k_l + ((size_t)b*6400 + kbase + (i+1)*64)*64, 64, t);
            asm volatile("cp.async.commit_group;" ::: "memory");
        }

        // ---- S = Q K^T : 3-term split, fused hi/lo B-frag loads ----
        float S[8][4];
        #pragma unroll
        for (int nt = 0; nt < 8; nt++)
            #pragma unroll
            for (int j = 0; j < 4; j++) S[nt][j] = 0.f;

        #pragma unroll
        for (int kb = 0; kb < 4; kb++) {
            uint32_t kf[8][4];
            #pragma unroll
            for (int nt = 0; nt < 8; nt++) {
                uint32_t R  = (uint32_t)(nt*8) + br;
                uint32_t ch = ((uint32_t)(kb*2) + bx) ^ br;
                ldmx4(kf[nt], kbuf + bpl + R*128u + ch*16u);
            }
            #pragma unroll
            for (int nt = 0; nt < 8; nt++) mma_bf16(S[nt], qh[kb], &kf[nt][0]);
            #pragma unroll
            for (int nt = 0; nt < 8; nt++) mma_bf16(S[nt], qh[kb], &kf[nt][2]);
            #pragma unroll
            for (int nt = 0; nt < 8; nt++) mma_bf16(S[nt], ql[kb], &kf[nt][0]);
        }

        // ---- softmax numerator: exp2 (theta pre-scaled), hi-only P pack ----
        uint32_t ph[4][4];
        #pragma unroll
        for (int nt = 0; nt < 8; nt++) {
            float p0 = ex2(S[nt][0]);
            float p1 = ex2(S[nt][1]);
            float p2 = ex2(S[nt][2]);
            float p3 = ex2(S[nt][3]);
            lsA += p0 + p1;
            lsB += p2 + p3;
            int kb = nt >> 1, hf = (nt & 1) * 2;
            ph[kb][hf + 0] = pack_bf16x2(p0, p1);
            ph[kb][hf + 1] = pack_bf16x2(p2, p3);
        }

        // V(i) ready (leave K(i+1) pending)
        if (i < NCHUNK-1) { asm volatile("cp.async.wait_group 1;" ::: "memory"); }
        else              { asm volatile("cp.async.wait_group 0;" ::: "memory"); }
        __syncthreads();

        // ---- O += P V : 2-term (Ph*Vh + Ph*Vl) ----
        #pragma unroll
        for (int kb = 0; kb < 4; kb++) {
            uint32_t vf[8][4];
            #pragma unroll
            for (int ct = 0; ct < 8; ct++) {
                uint32_t R  = (uint32_t)(ct*8) + br;
                uint32_t ch = ((uint32_t)(kb*2) + bx) ^ br;
                ldmx4(vf[ct], sb + PV0 + bpl + R*128u + ch*16u);
            }
            #pragma unroll
            for (int ct = 0; ct < 8; ct++) mma_bf16(O[ct], ph[kb], &vf[ct][0]);
            #pragma unroll
            for (int ct = 0; ct < 8; ct++) mma_bf16(O[ct], ph[kb], &vf[ct][2]);
        }

        __syncthreads();                       // all warps done reading V
        if (i < NCHUNK-1) {                    // prefetch V(i+1) over next S-GEMM
            ld_plane(sb + PV0,         g_v_h + (size_t)b*64*6400 + kbase + (i+1)*64, 6400, t);
            ld_plane(sb + PV0 + 8192u, g_v_l + (size_t)b*64*6400 + kbase + (i+1)*64, 6400, t);
            asm volatile("cp.async.commit_group;" ::: "memory");
        }
    }

    // ---- epilogue: write UNNORMALIZED partial O and partial row sums l ----
    lsA += __shfl_xor_sync(0xffffffffu, lsA, 1);
    lsA += __shfl_xor_sync(0xffffffffu, lsA, 2);
    lsB += __shfl_xor_sync(0xffffffffu, lsB, 1);
    lsB += __shfl_xor_sync(0xffffffffu, lsB, 2);

    float* gp = sp ? g_p1 : g_p0;
    float* gl = sp ? g_l1 : g_l0;
    const int gq = lane >> 2, tq = lane & 3;
    if (tq == 0) {
        gl[(size_t)b*6400 + n0 + m0 + gq    ] = lsA;
        gl[(size_t)b*6400 + n0 + m0 + gq + 8] = lsB;
    }

    __syncthreads();
    float* stg = (float*)(smem);            // 64x64 f32 staging = 16KB (bufA)
    #pragma unroll
    for (int ct = 0; ct < 8; ct++) {
        int c = ct*8 + 2*tq;
        stg[(c    )*64 + m0 + gq    ] = O[ct][0];
        stg[(c + 1)*64 + m0 + gq    ] = O[ct][1];
        stg[(c    )*64 + m0 + gq + 8] = O[ct][2];
        stg[(c + 1)*64 + m0 + gq + 8] = O[ct][3];
    }
    __syncthreads();
    for (int idx = t; idx < 1024; idx += 128) {
        int c = idx >> 4, chn = idx & 15;
        float4 v = *(float4*)&stg[c*64 + chn*4];
        *(float4*)&gp[((size_t)b*64 + c)*6400 + n0 + chn*4] = v;
    }
}

// ---------------- kernel 3: combine splits + W-conv + BN statistics ----------
__global__ __launch_bounds__(256) void convW_kernel(
    const float* __restrict__ wW, const float* __restrict__ bW)
{
    __shared__ __align__(16) float ys[64*68];
    __shared__ __align__(16) float ws[64*68];
    __shared__ float ssum[64], ssq[64], linv[64];
    const int b  = blockIdx.y;
    const int n0 = blockIdx.x * 64;
    const int t  = threadIdx.x;
    const int tx = t & 15, ty = t >> 4;

    if (t < 64) {
        linv[t] = 1.f / (g_l0[(size_t)b*6400 + n0 + t] + g_l1[(size_t)b*6400 + n0 + t]);
        ssum[t] = 0.f; ssq[t] = 0.f;
    }
    __syncthreads();

    const float* p0 = g_p0 + (size_t)b*64*6400;
    const float* p1 = g_p1 + (size_t)b*64*6400;
    for (int i = t; i < 4096; i += 256) {
        int c = i >> 6, n = i & 63;
        size_t idx = (size_t)c*6400 + n0 + n;
        ys[c*68 + n] = (p0[idx] + p1[idx]) * linv[n];
    }
    for (int i = t; i < 4096; i += 256) ws[(i & 63)*68 + (i >> 6)] = wW[i];
    __syncthreads();

    float acc[4][4];
    #pragma unroll
    for (int j = 0; j < 4; j++) {
        float bb = bW[4*tx + j];
        #pragma unroll
        for (int r = 0; r < 4; r++) acc[r][j] = bb;
    }
    #pragma unroll 4
    for (int c = 0; c < 64; c++) {
        float4 a  = *(const float4*)&ys[c*68 + 4*ty];
        float4 w4 = *(const float4*)&ws[c*68 + 4*tx];
        acc[0][0] += a.x*w4.x; acc[0][1] += a.x*w4.y; acc[0][2] += a.x*w4.z; acc[0][3] += a.x*w4.w;
        acc[1][0] += a.y*w4.x; acc[1][1] += a.y*w4.y; acc[1][2] += a.y*w4.z; acc[1][3] += a.y*w4.w;
        acc[2][0] += a.z*w4.x; acc[2][1] += a.z*w4.y; acc[2][2] += a.z*w4.z; acc[2][3] += a.z*w4.w;
        acc[3][0] += a.w*w4.x; acc[3][1] += a.w*w4.y; acc[3][2] += a.w*w4.z; acc[3][3] += a.w*w4.w;
    }
    float* dst = g_Wy + (size_t)b*64*6400;
    #pragma unroll
    for (int j = 0; j < 4; j++) {
        float4 v = make_float4(acc[0][j], acc[1][j], acc[2][j], acc[3][j]);
        *(float4*)&dst[(4*tx + j)*6400 + n0 + 4*ty] = v;
    }
    #pragma unroll
    for (int j = 0; j < 4; j++) {
        float s = 0.f, q = 0.f;
        #pragma unroll
        for (int r = 0; r < 4; r++) { s += acc[r][j]; q += acc[r][j]*acc[r][j]; }
        atomicAdd(&ssum[4*tx + j], s);
        atomicAdd(&ssq [4*tx + j], q);
    }
    __syncthreads();
    if (t < 64) {
        atomicAdd(&g_stats[t],      ssum[t]);
        atomicAdd(&g_stats[64 + t], ssq[t]);
    }
}

// ---------------- kernel 4: BN scale/shift + apply + residual (fused) --------
__global__ __launch_bounds__(256) void out_kernel(const float* __restrict__ x,
                                                  const float* __restrict__ gamma,
                                                  const float* __restrict__ beta,
                                                  float* __restrict__ out)
{
    int i   = blockIdx.x * 256 + threadIdx.x;
    int idx = i * 4;
    int c   = (idx / 6400) & 63;
    const float invN = 1.f / (float)(B_ * N_);
    float mean = g_stats[c] * invN;
    float var  = g_stats[64 + c] * invN - mean*mean;
    float sc   = gamma[c] * rsqrtf(var + 1e-5f);
    float sh   = beta[c] - mean*sc;
    float4 wy = *(const float4*)&g_Wy[idx];
    float4 xv = *(const float4*)&x[idx];
    float4 o;
    o.x = wy.x*sc + sh + xv.x;
    o.y = wy.y*sc + sh + xv.y;
    o.z = wy.z*sc + sh + xv.z;
    o.w = wy.w*sc + sh + xv.w;
    *(float4*)&out[idx] = o;
}

// ---------------- launch -------------------------------------------------------
extern "C" void kernel_launch(void* const* d_in, const int* in_sizes, int n_in,
                              void* d_out, int out_size)
{
    const float* x     = (const float*)d_in[0];
    const float* wt    = (const float*)d_in[1];
    const float* bt    = (const float*)d_in[2];
    const float* wp    = (const float*)d_in[3];
    const float* bp    = (const float*)d_in[4];
    const float* wg    = (const float*)d_in[5];
    const float* bg    = (const float*)d_in[6];
    const float* wW    = (const float*)d_in[7];
    const float* bW    = (const float*)d_in[8];
    const float* gamma = (const float*)d_in[9];
    const float* beta  = (const float*)d_in[10];

    dim3 gproj(100, B_);
    proj3_kernel <<<gproj, 256>>>(x, wt, bt, wp, bp, wg, bg);
    dim3 gflash(100, B_, 2);               // 800 CTAs: q-tile x batch x key-split
    flash_kernel <<<gflash, 128>>>();
    convW_kernel <<<gproj, 256>>>(wW, bW);
    out_kernel   <<<(B_*C_*N_)/4/256, 256>>>(x, gamma, beta, (float*)d_out);
}

// round 12
// speedup vs baseline: 1.0591x; 1.0591x over previous
#include <cuda_runtime.h>
#include <cuda_bf16.h>
#include <cstdint>

#define B_ 4
#define C_ 64
#define N_ 6400
#define LOG2E 1.4426950408889634f

// ---------------- device-global scratch -------------------------------------
__device__ __align__(16) __nv_bfloat16 g_q_h[B_*N_*C_];   // [B][N][C] (theta, pre-scaled by log2e)
__device__ __align__(16) __nv_bfloat16 g_q_l[B_*N_*C_];
__device__ __align__(16) __nv_bfloat16 g_k_h[B_*N_*C_];   // [B][N][C]
__device__ __align__(16) __nv_bfloat16 g_k_l[B_*N_*C_];
__device__ __align__(16) __nv_bfloat16 g_v_h[B_*C_*N_];   // [B][C][N]
__device__ __align__(16) __nv_bfloat16 g_v_l[B_*C_*N_];
__device__ __align__(16) float g_p0[B_*C_*N_];            // split-0 partial O (unnormalized)
__device__ __align__(16) float g_p1[B_*C_*N_];            // split-1 partial O
__device__ float g_l0[B_*N_];                              // split-0 partial row sums
__device__ float g_l1[B_*N_];
__device__ float g_Wy  [B_*C_*N_];
__device__ float g_stats[2*C_];

// ---------------- helpers ----------------------------------------------------
__device__ __forceinline__ uint32_t smem_u32(const void* p) {
    uint32_t a;
    asm("{ .reg .u64 t; cvta.to.shared.u64 t, %1; cvt.u32.u64 %0, t; }" : "=r"(a) : "l"(p));
    return a;
}
__device__ __forceinline__ void cpa16(uint32_t dst, const void* src) {
    asm volatile("cp.async.cg.shared.global [%0], [%1], 16;" :: "r"(dst), "l"(src));
}
__device__ __forceinline__ void mma_bf16(float* d, const uint32_t* a, const uint32_t* b) {
    asm volatile("mma.sync.aligned.m16n8k16.row.col.f32.bf16.bf16.f32 "
        "{%0,%1,%2,%3}, {%4,%5,%6,%7}, {%8,%9}, {%0,%1,%2,%3};"
        : "+f"(d[0]), "+f"(d[1]), "+f"(d[2]), "+f"(d[3])
        : "r"(a[0]), "r"(a[1]), "r"(a[2]), "r"(a[3]), "r"(b[0]), "r"(b[1]));
}
__device__ __forceinline__ void ldmx4(uint32_t* r, uint32_t a) {
    asm volatile("ldmatrix.sync.aligned.m8n8.x4.shared.b16 {%0,%1,%2,%3}, [%4];"
        : "=r"(r[0]), "=r"(r[1]), "=r"(r[2]), "=r"(r[3]) : "r"(a));
}
__device__ __forceinline__ float ex2(float x) {
    float r;
    asm("ex2.approx.f32 %0, %1;" : "=f"(r) : "f"(x));
    return r;
}
// pack (a,b) -> bf16x2 hi-plane + residual lo-plane (lo 16 bits = a)
__device__ __forceinline__ void split2(float a, float b, uint32_t& hi, uint32_t& lo) {
    uint32_t h;
    asm("cvt.rn.bf16x2.f32 %0, %1, %2;" : "=r"(h) : "f"(b), "f"(a));
    float ah = __uint_as_float(h << 16);
    float bh = __uint_as_float(h & 0xffff0000u);
    float al = a - ah, bl = b - bh;
    uint32_t l;
    asm("cvt.rn.bf16x2.f32 %0, %1, %2;" : "=r"(l) : "f"(bl), "f"(al));
    hi = h; lo = l;
}
__device__ __forceinline__ uint32_t pack_bf16x2(float a, float b) {
    uint32_t h;
    asm("cvt.rn.bf16x2.f32 %0, %1, %2;" : "=r"(h) : "f"(b), "f"(a));
    return h;
}

// ---------------- kernel 1: projections -> bf16 hi/lo planes ----------------
__global__ __launch_bounds__(256) void proj3_kernel(
    const float* __restrict__ x,
    const float* __restrict__ wt, const float* __restrict__ bt,
    const float* __restrict__ wp, const float* __restrict__ bp,
    const float* __restrict__ wg, const float* __restrict__ bg)
{
    __shared__ __align__(16) float xs[64*68];
    __shared__ __align__(16) float ws[64*68];
    const int b  = blockIdx.y;
    const int n0 = blockIdx.x * 64;
    const int t  = threadIdx.x;
    const int tx = t & 15, ty = t >> 4;

    if (blockIdx.x == 0 && b == 0 && t < 128) g_stats[t] = 0.f;

    for (int i = t; i < 4096; i += 256) {
        int c = i >> 6, n = i & 63;
        xs[c*68 + n] = x[((size_t)b*64 + c)*6400 + n0 + n];
    }
    const float* W[3]  = {wt, wp, wg};
    const float* BV[3] = {bt, bp, bg};

    for (int m = 0; m < 3; m++) {
        __syncthreads();
        for (int i = t; i < 4096; i += 256) ws[(i & 63)*68 + (i >> 6)] = W[m][i];
        __syncthreads();

        float acc[4][4];
        #pragma unroll
        for (int j = 0; j < 4; j++) {
            float bb = BV[m][4*tx + j];
            #pragma unroll
            for (int r = 0; r < 4; r++) acc[r][j] = bb;
        }
        #pragma unroll 4
        for (int c = 0; c < 64; c++) {
            float4 a  = *(const float4*)&xs[c*68 + 4*ty];
            float4 w4 = *(const float4*)&ws[c*68 + 4*tx];
            acc[0][0] += a.x*w4.x; acc[0][1] += a.x*w4.y; acc[0][2] += a.x*w4.z; acc[0][3] += a.x*w4.w;
            acc[1][0] += a.y*w4.x; acc[1][1] += a.y*w4.y; acc[1][2] += a.y*w4.z; acc[1][3] += a.y*w4.w;
            acc[2][0] += a.z*w4.x; acc[2][1] += a.z*w4.y; acc[2][2] += a.z*w4.z; acc[2][3] += a.z*w4.w;
            acc[3][0] += a.w*w4.x; acc[3][1] += a.w*w4.y; acc[3][2] += a.w*w4.z; acc[3][3] += a.w*w4.w;
        }
        if (m == 0) {    // theta: pre-scale by log2(e) so softmax uses ex2 directly
            #pragma unroll
            for (int r = 0; r < 4; r++)
                #pragma unroll
                for (int j = 0; j < 4; j++) acc[r][j] *= LOG2E;
        }
        if (m < 2) {
            __nv_bfloat16* ph = (m == 0) ? g_q_h : g_k_h;
            __nv_bfloat16* pl = (m == 0) ? g_q_l : g_k_l;
            #pragma unroll
            for (int r = 0; r < 4; r++) {
                uint32_t h01, l01, h23, l23;
                split2(acc[r][0], acc[r][1], h01, l01);
                split2(acc[r][2], acc[r][3], h23, l23);
                size_t idx = ((size_t)b*6400 + n0 + 4*ty + r)*64 + 4*tx;
                *(uint2*)&ph[idx] = make_uint2(h01, h23);
                *(uint2*)&pl[idx] = make_uint2(l01, l23);
            }
        } else {
            #pragma unroll
            for (int j = 0; j < 4; j++) {
                uint32_t hA, lA, hB, lB;
                split2(acc[0][j], acc[1][j], hA, lA);
                split2(acc[2][j], acc[3][j], hB, lB);
                size_t idx = ((size_t)b*64 + 4*tx + j)*6400 + n0 + 4*ty;
                *(uint2*)&g_v_h[idx] = make_uint2(hA, hB);
                *(uint2*)&g_v_l[idx] = make_uint2(lA, lB);
            }
        }
    }
}

// ---------------- kernel 2: flash attention, split-K over 2 halves ----------
// smem planes: 64 rows x 64 bf16 (128B rows, XOR-swizzled 16B chunks), 8KB each
#define PQH 0u
#define PQL 8192u
#define PKH 16384u
#define PKL 24576u
#define PVH 32768u
#define PVL 40960u
#define NCHUNK 50                  // 50 key-chunks of 64 per split

__device__ __forceinline__ void ld_plane(uint32_t dst, const __nv_bfloat16* src,
                                         int rowstride, int t)
{
    #pragma unroll
    for (int k = 0; k < 4; k++) {
        int idx = t + k*128;               // 512 chunks total
        int row = idx >> 3, ch = idx & 7;
        cpa16(dst + (uint32_t)row*128u + (uint32_t)((ch ^ (row & 7))*16),
              src + (size_t)row*rowstride + ch*8);
    }
}

__global__ __launch_bounds__(128, 4) void flash_kernel()
{
    __shared__ __align__(128) char smem[49152];
    const uint32_t sb = smem_u32(smem);
    const int t    = threadIdx.x;
    const int lane = t & 31;
    const int wid  = t >> 5;
    const int b    = blockIdx.y;
    const int n0   = blockIdx.x * 64;
    const int sp   = blockIdx.z;          // key-range split: 0 or 1
    const int kbase = sp * 3200;          // this split handles keys [kbase, kbase+3200)
    const int m0   = wid * 16;

    // prologue: group0 = {Q, K0}, group1 = {V0}
    ld_plane(sb + PQH, g_q_h + ((size_t)b*6400 + n0)*64, 64, t);
    ld_plane(sb + PQL, g_q_l + ((size_t)b*6400 + n0)*64, 64, t);
    ld_plane(sb + PKH, g_k_h + ((size_t)b*6400 + kbase)*64, 64, t);
    ld_plane(sb + PKL, g_k_l + ((size_t)b*6400 + kbase)*64, 64, t);
    asm volatile("cp.async.commit_group;" ::: "memory");
    ld_plane(sb + PVH, g_v_h + (size_t)b*64*6400 + kbase, 6400, t);
    ld_plane(sb + PVL, g_v_l + (size_t)b*64*6400 + kbase, 6400, t);
    asm volatile("cp.async.commit_group;" ::: "memory");

    // lane-derived ldmatrix address components
    const uint32_t ar   = (uint32_t)(lane & 7) + ((uint32_t)((lane >> 3) & 1) << 3);
    const uint32_t ax   = (uint32_t)((lane >> 4) & 1);
    const uint32_t axr  = (uint32_t)(lane & 7);
    const uint32_t br   = (uint32_t)(lane & 7);
    const uint32_t bx   = (uint32_t)((lane >> 3) & 1);
    const uint32_t bpl  = ((uint32_t)(lane >> 4) & 1) * 8192u;  // lanes 16-31 -> lo plane

    uint32_t qh[4][4], ql[4][4];
    float O[8][4];
    #pragma unroll
    for (int i = 0; i < 8; i++)
        #pragma unroll
        for (int j = 0; j < 4; j++) O[i][j] = 0.f;
    float lsA = 0.f, lsB = 0.f;

    #pragma unroll 1
    for (int i = 0; i < NCHUNK; i++) {
        // K(i) ready (leave V(i) pending)
        asm volatile("cp.async.wait_group 1;" ::: "memory");
        __syncthreads();

        if (i == 0) {
            #pragma unroll
            for (int kb = 0; kb < 4; kb++) {
                uint32_t R  = (uint32_t)m0 + ar;
                uint32_t ch = ((uint32_t)(kb*2) + ax) ^ axr;
                ldmx4(qh[kb], sb + PQH + R*128u + ch*16u);
                ldmx4(ql[kb], sb + PQL + R*128u + ch*16u);
            }
        }

        // ---- S = Q K^T : 3-term split, fused hi/lo B-frag loads ----
        float S[8][4];
        #pragma unroll
        for (int nt = 0; nt < 8; nt++)
            #pragma unroll
            for (int j = 0; j < 4; j++) S[nt][j] = 0.f;

        #pragma unroll
        for (int kb = 0; kb < 4; kb++) {
            uint32_t kf[8][4];
            #pragma unroll
            for (int nt = 0; nt < 8; nt++) {
                uint32_t R  = (uint32_t)(nt*8) + br;
                uint32_t ch = ((uint32_t)(kb*2) + bx) ^ br;
                ldmx4(kf[nt], sb + PKH + bpl + R*128u + ch*16u);
            }
            #pragma unroll
            for (int nt = 0; nt < 8; nt++) mma_bf16(S[nt], qh[kb], &kf[nt][0]);
            #pragma unroll
            for (int nt = 0; nt < 8; nt++) mma_bf16(S[nt], qh[kb], &kf[nt][2]);
            #pragma unroll
            for (int nt = 0; nt < 8; nt++) mma_bf16(S[nt], ql[kb], &kf[nt][0]);
        }

        __syncthreads();                       // all warps done reading K
        if (i < NCHUNK-1) {                    // prefetch K(i+1) over softmax+PV
            ld_plane(sb + PKH, g_k_h + ((size_t)b*6400 + kbase + (i+1)*64)*64, 64, t);
            ld_plane(sb + PKL, g_k_l + ((size_t)b*6400 + kbase + (i+1)*64)*64, 64, t);
            asm volatile("cp.async.commit_group;" ::: "memory");
        }

        // ---- softmax numerator: exp2 (theta pre-scaled), hi-only P pack ----
        uint32_t ph[4][4];
        #pragma unroll
        for (int nt = 0; nt < 8; nt++) {
            float p0 = ex2(S[nt][0]);
            float p1 = ex2(S[nt][1]);
            float p2 = ex2(S[nt][2]);
            float p3 = ex2(S[nt][3]);
            lsA += p0 + p1;
            lsB += p2 + p3;
            int kb = nt >> 1, hf = (nt & 1) * 2;
            ph[kb][hf + 0] = pack_bf16x2(p0, p1);
            ph[kb][hf + 1] = pack_bf16x2(p2, p3);
        }

        // V(i) ready (leave K(i+1) pending)
        if (i < NCHUNK-1) { asm volatile("cp.async.wait_group 1;" ::: "memory"); }
        else              { asm volatile("cp.async.wait_group 0;" ::: "memory"); }
        __syncthreads();

        // ---- O += P V : 2-term (Ph*Vh + Ph*Vl) ----
        #pragma unroll
        for (int kb = 0; kb < 4; kb++) {
            uint32_t vf[8][4];
            #pragma unroll
            for (int ct = 0; ct < 8; ct++) {
                uint32_t R  = (uint32_t)(ct*8) + br;
                uint32_t ch = ((uint32_t)(kb*2) + bx) ^ br;
                ldmx4(vf[ct], sb + PVH + bpl + R*128u + ch*16u);
            }
            #pragma unroll
            for (int ct = 0; ct < 8; ct++) mma_bf16(O[ct], ph[kb], &vf[ct][0]);
            #pragma unroll
            for (int ct = 0; ct < 8; ct++) mma_bf16(O[ct], ph[kb], &vf[ct][2]);
        }

        __syncthreads();                       // all warps done reading V
        if (i < NCHUNK-1) {                    // prefetch V(i+1) over next S-GEMM
            ld_plane(sb + PVH, g_v_h + (size_t)b*64*6400 + kbase + (i+1)*64, 6400, t);
            ld_plane(sb + PVL, g_v_l + (size_t)b*64*6400 + kbase + (i+1)*64, 6400, t);
            asm volatile("cp.async.commit_group;" ::: "memory");
        }
    }

    // ---- epilogue: write UNNORMALIZED partial O and partial row sums l ----
    lsA += __shfl_xor_sync(0xffffffffu, lsA, 1);
    lsA += __shfl_xor_sync(0xffffffffu, lsA, 2);
    lsB += __shfl_xor_sync(0xffffffffu, lsB, 1);
    lsB += __shfl_xor_sync(0xffffffffu, lsB, 2);

    float* gp = sp ? g_p1 : g_p0;
    float* gl = sp ? g_l1 : g_l0;
    const int gq = lane >> 2, tq = lane & 3;
    if (tq == 0) {
        gl[(size_t)b*6400 + n0 + m0 + gq    ] = lsA;
        gl[(size_t)b*6400 + n0 + m0 + gq + 8] = lsB;
    }

    __syncthreads();
    float* stg = (float*)(smem + PKH);      // 64x64 f32 staging = 16KB
    #pragma unroll
    for (int ct = 0; ct < 8; ct++) {
        int c = ct*8 + 2*tq;
        stg[(c    )*64 + m0 + gq    ] = O[ct][0];
        stg[(c + 1)*64 + m0 + gq    ] = O[ct][1];
        stg[(c    )*64 + m0 + gq + 8] = O[ct][2];
        stg[(c + 1)*64 + m0 + gq + 8] = O[ct][3];
    }
    __syncthreads();
    for (int idx = t; idx < 1024; idx += 128) {
        int c = idx >> 4, chn = idx & 15;
        float4 v = *(float4*)&stg[c*64 + chn*4];
        *(float4*)&gp[((size_t)b*64 + c)*6400 + n0 + chn*4] = v;
    }
}

// ---------------- kernel 3: combine splits + W-conv + BN statistics ----------
__global__ __launch_bounds__(256) void convW_kernel(
    const float* __restrict__ wW, const float* __restrict__ bW)
{
    __shared__ __align__(16) float ys[64*68];
    __shared__ __align__(16) float ws[64*68];
    __shared__ float ssum[64], ssq[64], linv[64];
    const int b  = blockIdx.y;
    const int n0 = blockIdx.x * 64;
    const int t  = threadIdx.x;
    const int tx = t & 15, ty = t >> 4;

    if (t < 64) {
        linv[t] = 1.f / (g_l0[(size_t)b*6400 + n0 + t] + g_l1[(size_t)b*6400 + n0 + t]);
        ssum[t] = 0.f; ssq[t] = 0.f;
    }
    __syncthreads();

    const float* p0 = g_p0 + (size_t)b*64*6400;
    const float* p1 = g_p1 + (size_t)b*64*6400;
    for (int i = t; i < 4096; i += 256) {
        int c = i >> 6, n = i & 63;
        size_t idx = (size_t)c*6400 + n0 + n;
        ys[c*68 + n] = (p0[idx] + p1[idx]) * linv[n];
    }
    for (int i = t; i < 4096; i += 256) ws[(i & 63)*68 + (i >> 6)] = wW[i];
    __syncthreads();

    float acc[4][4];
    #pragma unroll
    for (int j = 0; j < 4; j++) {
        float bb = bW[4*tx + j];
        #pragma unroll
        for (int r = 0; r < 4; r++) acc[r][j] = bb;
    }
    #pragma unroll 4
    for (int c = 0; c < 64; c++) {
        float4 a  = *(const float4*)&ys[c*68 + 4*ty];
        float4 w4 = *(const float4*)&ws[c*68 + 4*tx];
        acc[0][0] += a.x*w4.x; acc[0][1] += a.x*w4.y; acc[0][2] += a.x*w4.z; acc[0][3] += a.x*w4.w;
        acc[1][0] += a.y*w4.x; acc[1][1] += a.y*w4.y; acc[1][2] += a.y*w4.z; acc[1][3] += a.y*w4.w;
        acc[2][0] += a.z*w4.x; acc[2][1] += a.z*w4.y; acc[2][2] += a.z*w4.z; acc[2][3] += a.z*w4.w;
        acc[3][0] += a.w*w4.x; acc[3][1] += a.w*w4.y; acc[3][2] += a.w*w4.z; acc[3][3] += a.w*w4.w;
    }
    float* dst = g_Wy + (size_t)b*64*6400;
    #pragma unroll
    for (int j = 0; j < 4; j++) {
        float4 v = make_float4(acc[0][j], acc[1][j], acc[2][j], acc[3][j]);
        *(float4*)&dst[(4*tx + j)*6400 + n0 + 4*ty] = v;
    }
    #pragma unroll
    for (int j = 0; j < 4; j++) {
        float s = 0.f, q = 0.f;
        #pragma unroll
        for (int r = 0; r < 4; r++) { s += acc[r][j]; q += acc[r][j]*acc[r][j]; }
        atomicAdd(&ssum[4*tx + j], s);
        atomicAdd(&ssq [4*tx + j], q);
    }
    __syncthreads();
    if (t < 64) {
        atomicAdd(&g_stats[t],      ssum[t]);
        atomicAdd(&g_stats[64 + t], ssq[t]);
    }
}

// ---------------- kernel 4: BN scale/shift + apply + residual (fused) --------
__global__ __launch_bounds__(256) void out_kernel(const float* __restrict__ x,
                                                  const float* __restrict__ gamma,
                                                  const float* __restrict__ beta,
                                                  float* __restrict__ out)
{
    int i   = blockIdx.x * 256 + threadIdx.x;
    int idx = i * 4;
    int c   = (idx / 6400) & 63;
    const float invN = 1.f / (float)(B_ * N_);
    float mean = g_stats[c] * invN;
    float var  = g_stats[64 + c] * invN - mean*mean;
    float sc   = gamma[c] * rsqrtf(var + 1e-5f);
    float sh   = beta[c] - mean*sc;
    float4 wy = *(const float4*)&g_Wy[idx];
    float4 xv = *(const float4*)&x[idx];
    float4 o;
    o.x = wy.x*sc + sh + xv.x;
    o.y = wy.y*sc + sh + xv.y;
    o.z = wy.z*sc + sh + xv.z;
    o.w = wy.w*sc + sh + xv.w;
    *(float4*)&out[idx] = o;
}

// ---------------- launch -------------------------------------------------------
extern "C" void kernel_launch(void* const* d_in, const int* in_sizes, int n_in,
                              void* d_out, int out_size)
{
    const float* x     = (const float*)d_in[0];
    const float* wt    = (const float*)d_in[1];
    const float* bt    = (const float*)d_in[2];
    const float* wp    = (const float*)d_in[3];
    const float* bp    = (const float*)d_in[4];
    const float* wg    = (const float*)d_in[5];
    const float* bg    = (const float*)d_in[6];
    const float* wW    = (const float*)d_in[7];
    const float* bW    = (const float*)d_in[8];
    const float* gamma = (const float*)d_in[9];
    const float* beta  = (const float*)d_in[10];

    dim3 gproj(100, B_);
    proj3_kernel <<<gproj, 256>>>(x, wt, bt, wp, bp, wg, bg);
    dim3 gflash(100, B_, 2);               // 800 CTAs: q-tile x batch x key-split
    flash_kernel <<<gflash, 128>>>();
    convW_kernel <<<gproj, 256>>>(wW, bW);
    out_kernel   <<<(B_*C_*N_)/4/256, 256>>>(x, gamma, beta, (float*)d_out);
}

// round 13
// speedup vs baseline: 1.1419x; 1.0782x over previous
#include <cuda_runtime.h>
#include <cuda_bf16.h>
#include <cstdint>

#define B_ 4
#define C_ 64
#define N_ 6400
#define LOG2E 1.4426950408889634f

// ---------------- device-global scratch -------------------------------------
__device__ __align__(16) __nv_bfloat16 g_q_h[B_*N_*C_];   // [B][N][C] (theta, pre-scaled by log2e)
__device__ __align__(16) __nv_bfloat16 g_q_l[B_*N_*C_];
__device__ __align__(16) __nv_bfloat16 g_k_h[B_*N_*C_];   // [B][N][C]
__device__ __align__(16) __nv_bfloat16 g_k_l[B_*N_*C_];
__device__ __align__(16) __nv_bfloat16 g_v_h[B_*C_*N_];   // [B][C][N]
__device__ __align__(16) __nv_bfloat16 g_v_l[B_*C_*N_];
__device__ __align__(16) float g_p[3][B_*C_*N_];          // per-split partial O (unnormalized)
__device__ float g_l[3][B_*N_];                            // per-split partial row sums
__device__ float g_Wy  [B_*C_*N_];
__device__ float g_stats[2*C_];

// ---------------- helpers ----------------------------------------------------
__device__ __forceinline__ uint32_t smem_u32(const void* p) {
    uint32_t a;
    asm("{ .reg .u64 t; cvta.to.shared.u64 t, %1; cvt.u32.u64 %0, t; }" : "=r"(a) : "l"(p));
    return a;
}
__device__ __forceinline__ void cpa16(uint32_t dst, const void* src) {
    asm volatile("cp.async.cg.shared.global [%0], [%1], 16;" :: "r"(dst), "l"(src));
}
__device__ __forceinline__ void mma_bf16(float* d, const uint32_t* a, const uint32_t* b) {
    asm volatile("mma.sync.aligned.m16n8k16.row.col.f32.bf16.bf16.f32 "
        "{%0,%1,%2,%3}, {%4,%5,%6,%7}, {%8,%9}, {%0,%1,%2,%3};"
        : "+f"(d[0]), "+f"(d[1]), "+f"(d[2]), "+f"(d[3])
        : "r"(a[0]), "r"(a[1]), "r"(a[2]), "r"(a[3]), "r"(b[0]), "r"(b[1]));
}
__device__ __forceinline__ void ldmx4(uint32_t* r, uint32_t a) {
    asm volatile("ldmatrix.sync.aligned.m8n8.x4.shared.b16 {%0,%1,%2,%3}, [%4];"
        : "=r"(r[0]), "=r"(r[1]), "=r"(r[2]), "=r"(r[3]) : "r"(a));
}
__device__ __forceinline__ float ex2(float x) {
    float r;
    asm("ex2.approx.f32 %0, %1;" : "=f"(r) : "f"(x));
    return r;
}
// pack (a,b) -> bf16x2 hi-plane + residual lo-plane (lo 16 bits = a)
__device__ __forceinline__ void split2(float a, float b, uint32_t& hi, uint32_t& lo) {
    uint32_t h;
    asm("cvt.rn.bf16x2.f32 %0, %1, %2;" : "=r"(h) : "f"(b), "f"(a));
    float ah = __uint_as_float(h << 16);
    float bh = __uint_as_float(h & 0xffff0000u);
    float al = a - ah, bl = b - bh;
    uint32_t l;
    asm("cvt.rn.bf16x2.f32 %0, %1, %2;" : "=r"(l) : "f"(bl), "f"(al));
    hi = h; lo = l;
}
__device__ __forceinline__ uint32_t pack_bf16x2(float a, float b) {
    uint32_t h;
    asm("cvt.rn.bf16x2.f32 %0, %1, %2;" : "=r"(h) : "f"(b), "f"(a));
    return h;
}

// ---------------- kernel 1: projections -> bf16 hi/lo planes ----------------
__global__ __launch_bounds__(256) void proj3_kernel(
    const float* __restrict__ x,
    const float* __restrict__ wt, const float* __restrict__ bt,
    const float* __restrict__ wp, const float* __restrict__ bp,
    const float* __restrict__ wg, const float* __restrict__ bg)
{
    __shared__ __align__(16) float xs[64*68];
    __shared__ __align__(16) float ws[64*68];
    const int b  = blockIdx.y;
    const int n0 = blockIdx.x * 64;
    const int t  = threadIdx.x;
    const int tx = t & 15, ty = t >> 4;

    if (blockIdx.x == 0 && b == 0 && t < 128) g_stats[t] = 0.f;

    for (int i = t; i < 4096; i += 256) {
        int c = i >> 6, n = i & 63;
        xs[c*68 + n] = x[((size_t)b*64 + c)*6400 + n0 + n];
    }
    const float* W[3]  = {wt, wp, wg};
    const float* BV[3] = {bt, bp, bg};

    for (int m = 0; m < 3; m++) {
        __syncthreads();
        for (int i = t; i < 4096; i += 256) ws[(i & 63)*68 + (i >> 6)] = W[m][i];
        __syncthreads();

        float acc[4][4];
        #pragma unroll
        for (int j = 0; j < 4; j++) {
            float bb = BV[m][4*tx + j];
            #pragma unroll
            for (int r = 0; r < 4; r++) acc[r][j] = bb;
        }
        #pragma unroll 4
        for (int c = 0; c < 64; c++) {
            float4 a  = *(const float4*)&xs[c*68 + 4*ty];
            float4 w4 = *(const float4*)&ws[c*68 + 4*tx];
            acc[0][0] += a.x*w4.x; acc[0][1] += a.x*w4.y; acc[0][2] += a.x*w4.z; acc[0][3] += a.x*w4.w;
            acc[1][0] += a.y*w4.x; acc[1][1] += a.y*w4.y; acc[1][2] += a.y*w4.z; acc[1][3] += a.y*w4.w;
            acc[2][0] += a.z*w4.x; acc[2][1] += a.z*w4.y; acc[2][2] += a.z*w4.z; acc[2][3] += a.z*w4.w;
            acc[3][0] += a.w*w4.x; acc[3][1] += a.w*w4.y; acc[3][2] += a.w*w4.z; acc[3][3] += a.w*w4.w;
        }
        if (m == 0) {    // theta: pre-scale by log2(e) so softmax uses ex2 directly
            #pragma unroll
            for (int r = 0; r < 4; r++)
                #pragma unroll
                for (int j = 0; j < 4; j++) acc[r][j] *= LOG2E;
        }
        if (m < 2) {
            __nv_bfloat16* ph = (m == 0) ? g_q_h : g_k_h;
            __nv_bfloat16* pl = (m == 0) ? g_q_l : g_k_l;
            #pragma unroll
            for (int r = 0; r < 4; r++) {
                uint32_t h01, l01, h23, l23;
                split2(acc[r][0], acc[r][1], h01, l01);
                split2(acc[r][2], acc[r][3], h23, l23);
                size_t idx = ((size_t)b*6400 + n0 + 4*ty + r)*64 + 4*tx;
                *(uint2*)&ph[idx] = make_uint2(h01, h23);
                *(uint2*)&pl[idx] = make_uint2(l01, l23);
            }
        } else {
            #pragma unroll
            for (int j = 0; j < 4; j++) {
                uint32_t hA, lA, hB, lB;
                split2(acc[0][j], acc[1][j], hA, lA);
                split2(acc[2][j], acc[3][j], hB, lB);
                size_t idx = ((size_t)b*64 + 4*tx + j)*6400 + n0 + 4*ty;
                *(uint2*)&g_v_h[idx] = make_uint2(hA, hB);
                *(uint2*)&g_v_l[idx] = make_uint2(lA, lB);
            }
        }
    }
}

// ---------------- kernel 2: flash attention, split-K(3), V ping-pong --------
// smem: PQ (Q; V-odd after chunk 0) 0..16K, PK 16K..32K, PV (V-even) 32K..48K
// each region = hi plane (8K) + lo plane (8K); 64 rows x 128B, XOR swizzle
#define PQH 0u
#define PQL 8192u
#define PKH 16384u
#define PKL 24576u
#define PVH 32768u
#define PVL 40960u

__device__ __forceinline__ void ld_plane(uint32_t dst, const __nv_bfloat16* src,
                                         int rowstride, int t)
{
    #pragma unroll
    for (int k = 0; k < 4; k++) {
        int idx = t + k*128;               // 512 chunks total
        int row = idx >> 3, ch = idx & 7;
        cpa16(dst + (uint32_t)row*128u + (uint32_t)((ch ^ (row & 7))*16),
              src + (size_t)row*rowstride + ch*8);
    }
}

__global__ __launch_bounds__(128, 4) void flash_kernel()
{
    __shared__ __align__(128) char smem[49152];
    const uint32_t sb = smem_u32(smem);
    const int t    = threadIdx.x;
    const int lane = t & 31;
    const int wid  = t >> 5;
    const int b    = blockIdx.y;
    const int n0   = blockIdx.x * 64;
    const int sp   = blockIdx.z;                      // key-range split: 0,1,2
    const int coff = (sp == 0) ? 0 : (sp == 1) ? 34 : 67;   // chunk offset
    const int nch  = (sp == 0) ? 34 : 33;                    // chunks this split
    const int kbase = coff * 64;
    const int m0   = wid * 16;

    // prologue: ONE group = {Q, K0, V0}
    ld_plane(sb + PQH, g_q_h + ((size_t)b*6400 + n0)*64, 64, t);
    ld_plane(sb + PQL, g_q_l + ((size_t)b*6400 + n0)*64, 64, t);
    ld_plane(sb + PKH, g_k_h + ((size_t)b*6400 + kbase)*64, 64, t);
    ld_plane(sb + PKL, g_k_l + ((size_t)b*6400 + kbase)*64, 64, t);
    ld_plane(sb + PVH, g_v_h + (size_t)b*64*6400 + kbase, 6400, t);
    ld_plane(sb + PVL, g_v_l + (size_t)b*64*6400 + kbase, 6400, t);
    asm volatile("cp.async.commit_group;" ::: "memory");

    // lane-derived ldmatrix address components
    const uint32_t ar   = (uint32_t)(lane & 7) + ((uint32_t)((lane >> 3) & 1) << 3);
    const uint32_t ax   = (uint32_t)((lane >> 4) & 1);
    const uint32_t axr  = (uint32_t)(lane & 7);
    const uint32_t br   = (uint32_t)(lane & 7);
    const uint32_t bx   = (uint32_t)((lane >> 3) & 1);
    const uint32_t bpl  = ((uint32_t)(lane >> 4) & 1) * 8192u;  // lanes 16-31 -> lo plane

    uint32_t qh[4][4], ql[4][4];
    float O[8][4];
    #pragma unroll
    for (int i = 0; i < 8; i++)
        #pragma unroll
        for (int j = 0; j < 4; j++) O[i][j] = 0.f;
    float lsA = 0.f, lsB = 0.f;

    #pragma unroll 1
    for (int i = 0; i < nch; i++) {
        // K(i) and V(i) landed (single group per chunk)
        asm volatile("cp.async.wait_group 0;" ::: "memory");
        __syncthreads();

        if (i == 0) {
            #pragma unroll
            for (int kb = 0; kb < 4; kb++) {
                uint32_t R  = (uint32_t)m0 + ar;
                uint32_t ch = ((uint32_t)(kb*2) + ax) ^ axr;
                ldmx4(qh[kb], sb + PQH + R*128u + ch*16u);
                ldmx4(ql[kb], sb + PQL + R*128u + ch*16u);
            }
        }
        const uint32_t vbuf = sb + ((i & 1) ? PQH : PVH);   // V(i) location

        // ---- S = Q K^T : 3-term split, fused hi/lo B-frag loads ----
        float S[8][4];
        #pragma unroll
        for (int nt = 0; nt < 8; nt++)
            #pragma unroll
            for (int j = 0; j < 4; j++) S[nt][j] = 0.f;

        #pragma unroll
        for (int kb = 0; kb < 4; kb++) {
            uint32_t kf[8][4];
            #pragma unroll
            for (int nt = 0; nt < 8; nt++) {
                uint32_t R  = (uint32_t)(nt*8) + br;
                uint32_t ch = ((uint32_t)(kb*2) + bx) ^ br;
                ldmx4(kf[nt], sb + PKH + bpl + R*128u + ch*16u);
            }
            #pragma unroll
            for (int nt = 0; nt < 8; nt++) mma_bf16(S[nt], qh[kb], &kf[nt][0]);
            #pragma unroll
            for (int nt = 0; nt < 8; nt++) mma_bf16(S[nt], qh[kb], &kf[nt][2]);
            #pragma unroll
            for (int nt = 0; nt < 8; nt++) mma_bf16(S[nt], ql[kb], &kf[nt][0]);
        }

        __syncthreads();       // K readers done (i==0: Q-frag readers done too)
        if (i < nch - 1) {     // prefetch K(i+1) and V(i+1) over softmax+PV
            ld_plane(sb + PKH, g_k_h + ((size_t)b*6400 + kbase + (i+1)*64)*64, 64, t);
            ld_plane(sb + PKL, g_k_l + ((size_t)b*6400 + kbase + (i+1)*64)*64, 64, t);
            uint32_t nv = sb + (((i + 1) & 1) ? PQH : PVH);
            ld_plane(nv,         g_v_h + (size_t)b*64*6400 + kbase + (i+1)*64, 6400, t);
            ld_plane(nv + 8192u, g_v_l + (size_t)b*64*6400 + kbase + (i+1)*64, 6400, t);
            asm volatile("cp.async.commit_group;" ::: "memory");
        }

        // ---- softmax numerator: exp2 (theta pre-scaled), hi-only P pack ----
        uint32_t ph[4][4];
        #pragma unroll
        for (int nt = 0; nt < 8; nt++) {
            float p0 = ex2(S[nt][0]);
            float p1 = ex2(S[nt][1]);
            float p2 = ex2(S[nt][2]);
            float p3 = ex2(S[nt][3]);
            lsA += p0 + p1;
            lsB += p2 + p3;
            int kb = nt >> 1, hf = (nt & 1) * 2;
            ph[kb][hf + 0] = pack_bf16x2(p0, p1);
            ph[kb][hf + 1] = pack_bf16x2(p2, p3);
        }

        // ---- O += P V : 2-term (Ph*Vh + Ph*Vl); no trailing sync needed ----
        #pragma unroll
        for (int kb = 0; kb < 4; kb++) {
            uint32_t vf[8][4];
            #pragma unroll
            for (int ct = 0; ct < 8; ct++) {
                uint32_t R  = (uint32_t)(ct*8) + br;
                uint32_t ch = ((uint32_t)(kb*2) + bx) ^ br;
                ldmx4(vf[ct], vbuf + bpl + R*128u + ch*16u);
            }
            #pragma unroll
            for (int ct = 0; ct < 8; ct++) mma_bf16(O[ct], ph[kb], &vf[ct][0]);
            #pragma unroll
            for (int ct = 0; ct < 8; ct++) mma_bf16(O[ct], ph[kb], &vf[ct][2]);
        }
    }

    // ---- epilogue: write UNNORMALIZED partial O and partial row sums l ----
    lsA += __shfl_xor_sync(0xffffffffu, lsA, 1);
    lsA += __shfl_xor_sync(0xffffffffu, lsA, 2);
    lsB += __shfl_xor_sync(0xffffffffu, lsB, 1);
    lsB += __shfl_xor_sync(0xffffffffu, lsB, 2);

    const int gq = lane >> 2, tq = lane & 3;
    if (tq == 0) {
        g_l[sp][(size_t)b*6400 + n0 + m0 + gq    ] = lsA;
        g_l[sp][(size_t)b*6400 + n0 + m0 + gq + 8] = lsB;
    }

    __syncthreads();
    float* stg = (float*)(smem + PKH);      // 64x64 f32 staging = 16KB (K region)
    #pragma unroll
    for (int ct = 0; ct < 8; ct++) {
        int c = ct*8 + 2*tq;
        stg[(c    )*64 + m0 + gq    ] = O[ct][0];
        stg[(c + 1)*64 + m0 + gq    ] = O[ct][1];
        stg[(c    )*64 + m0 + gq + 8] = O[ct][2];
        stg[(c + 1)*64 + m0 + gq + 8] = O[ct][3];
    }
    __syncthreads();
    for (int idx = t; idx < 1024; idx += 128) {
        int c = idx >> 4, chn = idx & 15;
        float4 v = *(float4*)&stg[c*64 + chn*4];
        *(float4*)&g_p[sp][((size_t)b*64 + c)*6400 + n0 + chn*4] = v;
    }
}

// ---------------- kernel 3: combine splits + W-conv + BN statistics ----------
__global__ __launch_bounds__(256) void convW_kernel(
    const float* __restrict__ wW, const float* __restrict__ bW)
{
    __shared__ __align__(16) float ys[64*68];
    __shared__ __align__(16) float ws[64*68];
    __shared__ float ssum[64], ssq[64], linv[64];
    const int b  = blockIdx.y;
    const int n0 = blockIdx.x * 64;
    const int t  = threadIdx.x;
    const int tx = t & 15, ty = t >> 4;

    if (t < 64) {
        size_t li = (size_t)b*6400 + n0 + t;
        linv[t] = 1.f / (g_l[0][li] + g_l[1][li] + g_l[2][li]);
        ssum[t] = 0.f; ssq[t] = 0.f;
    }
    __syncthreads();

    const float* p0 = g_p[0] + (size_t)b*64*6400;
    const float* p1 = g_p[1] + (size_t)b*64*6400;
    const float* p2 = g_p[2] + (size_t)b*64*6400;
    for (int i = t; i < 4096; i += 256) {
        int c = i >> 6, n = i & 63;
        size_t idx = (size_t)c*6400 + n0 + n;
        ys[c*68 + n] = (p0[idx] + p1[idx] + p2[idx]) * linv[n];
    }
    for (int i = t; i < 4096; i += 256) ws[(i & 63)*68 + (i >> 6)] = wW[i];
    __syncthreads();

    float acc[4][4];
    #pragma unroll
    for (int j = 0; j < 4; j++) {
        float bb = bW[4*tx + j];
        #pragma unroll
        for (int r = 0; r < 4; r++) acc[r][j] = bb;
    }
    #pragma unroll 4
    for (int c = 0; c < 64; c++) {
        float4 a  = *(const float4*)&ys[c*68 + 4*ty];
        float4 w4 = *(const float4*)&ws[c*68 + 4*tx];
        acc[0][0] += a.x*w4.x; acc[0][1] += a.x*w4.y; acc[0][2] += a.x*w4.z; acc[0][3] += a.x*w4.w;
        acc[1][0] += a.y*w4.x; acc[1][1] += a.y*w4.y; acc[1][2] += a.y*w4.z; acc[1][3] += a.y*w4.w;
        acc[2][0] += a.z*w4.x; acc[2][1] += a.z*w4.y; acc[2][2] += a.z*w4.z; acc[2][3] += a.z*w4.w;
        acc[3][0] += a.w*w4.x; acc[3][1] += a.w*w4.y; acc[3][2] += a.w*w4.z; acc[3][3] += a.w*w4.w;
    }
    float* dst = g_Wy + (size_t)b*64*6400;
    #pragma unroll
    for (int j = 0; j < 4; j++) {
        float4 v = make_float4(acc[0][j], acc[1][j], acc[2][j], acc[3][j]);
        *(float4*)&dst[(4*tx + j)*6400 + n0 + 4*ty] = v;
    }
    #pragma unroll
    for (int j = 0; j < 4; j++) {
        float s = 0.f, q = 0.f;
        #pragma unroll
        for (int r = 0; r < 4; r++) { s += acc[r][j]; q += acc[r][j]*acc[r][j]; }
        atomicAdd(&ssum[4*tx + j], s);
        atomicAdd(&ssq [4*tx + j], q);
    }
    __syncthreads();
    if (t < 64) {
        atomicAdd(&g_stats[t],      ssum[t]);
        atomicAdd(&g_stats[64 + t], ssq[t]);
    }
}

// ---------------- kernel 4: BN scale/shift + apply + residual (fused) --------
__global__ __launch_bounds__(256) void out_kernel(const float* __restrict__ x,
                                                  const float* __restrict__ gamma,
                                                  const float* __restrict__ beta,
                                                  float* __restrict__ out)
{
    int i   = blockIdx.x * 256 + threadIdx.x;
    int idx = i * 4;
    int c   = (idx / 6400) & 63;
    const float invN = 1.f / (float)(B_ * N_);
    float mean = g_stats[c] * invN;
    float var  = g_stats[64 + c] * invN - mean*mean;
    float sc   = gamma[c] * rsqrtf(var + 1e-5f);
    float sh   = beta[c] - mean*sc;
    float4 wy = *(const float4*)&g_Wy[idx];
    float4 xv = *(const float4*)&x[idx];
    float4 o;
    o.x = wy.x*sc + sh + xv.x;
    o.y = wy.y*sc + sh + xv.y;
    o.z = wy.z*sc + sh + xv.z;
    o.w = wy.w*sc + sh + xv.w;
    *(float4*)&out[idx] = o;
}

// ---------------- launch -------------------------------------------------------
extern "C" void kernel_launch(void* const* d_in, const int* in_sizes, int n_in,
                              void* d_out, int out_size)
{
    const float* x     = (const float*)d_in[0];
    const float* wt    = (const float*)d_in[1];
    const float* bt    = (const float*)d_in[2];
    const float* wp    = (const float*)d_in[3];
    const float* bp    = (const float*)d_in[4];
    const float* wg    = (const float*)d_in[5];
    const float* bg    = (const float*)d_in[6];
    const float* wW    = (const float*)d_in[7];
    const float* bW    = (const float*)d_in[8];
    const float* gamma = (const float*)d_in[9];
    const float* beta  = (const float*)d_in[10];

    dim3 gproj(100, B_);
    proj3_kernel <<<gproj, 256>>>(x, wt, bt, wp, bp, wg, bg);
    dim3 gflash(100, B_, 3);               // 1200 CTAs: q-tile x batch x key-split
    flash_kernel <<<gflash, 128>>>();
    convW_kernel <<<gproj, 256>>>(wW, bW);
    out_kernel   <<<(B_*C_*N_)/4/256, 256>>>(x, gamma, beta, (float*)d_out);
}

// round 14
// speedup vs baseline: 1.1489x; 1.0061x over previous
#include <cuda_runtime.h>
#include <cuda_bf16.h>
#include <cstdint>

#define B_ 4
#define C_ 64
#define N_ 6400
#define LOG2E 1.4426950408889634f

// ---------------- device-global scratch -------------------------------------
__device__ __align__(16) __nv_bfloat16 g_q_h[B_*N_*C_];   // [B][N][C] (theta, pre-scaled by log2e)
__device__ __align__(16) __nv_bfloat16 g_q_l[B_*N_*C_];
__device__ __align__(16) __nv_bfloat16 g_k_h[B_*N_*C_];   // [B][N][C]
__device__ __align__(16) __nv_bfloat16 g_k_l[B_*N_*C_];
__device__ __align__(16) __nv_bfloat16 g_v_h[B_*C_*N_];   // [B][C][N]
__device__ __align__(16) __nv_bfloat16 g_v_l[B_*C_*N_];
__device__ __align__(16) float g_p[3][B_*C_*N_];          // per-split partial O (unnormalized)
__device__ float g_l[3][B_*N_];                            // per-split partial row sums
__device__ float g_Wy  [B_*C_*N_];
__device__ float g_stats[2*C_];

// ---------------- helpers ----------------------------------------------------
__device__ __forceinline__ uint32_t smem_u32(const void* p) {
    uint32_t a;
    asm("{ .reg .u64 t; cvta.to.shared.u64 t, %1; cvt.u32.u64 %0, t; }" : "=r"(a) : "l"(p));
    return a;
}
__device__ __forceinline__ void cpa16(uint32_t dst, const void* src) {
    asm volatile("cp.async.cg.shared.global [%0], [%1], 16;" :: "r"(dst), "l"(src));
}
__device__ __forceinline__ void mma_bf16(float* d, const uint32_t* a, const uint32_t* b) {
    asm volatile("mma.sync.aligned.m16n8k16.row.col.f32.bf16.bf16.f32 "
        "{%0,%1,%2,%3}, {%4,%5,%6,%7}, {%8,%9}, {%0,%1,%2,%3};"
        : "+f"(d[0]), "+f"(d[1]), "+f"(d[2]), "+f"(d[3])
        : "r"(a[0]), "r"(a[1]), "r"(a[2]), "r"(a[3]), "r"(b[0]), "r"(b[1]));
}
__device__ __forceinline__ void ldmx4(uint32_t* r, uint32_t a) {
    asm volatile("ldmatrix.sync.aligned.m8n8.x4.shared.b16 {%0,%1,%2,%3}, [%4];"
        : "=r"(r[0]), "=r"(r[1]), "=r"(r[2]), "=r"(r[3]) : "r"(a));
}
__device__ __forceinline__ float ex2(float x) {
    float r;
    asm("ex2.approx.f32 %0, %1;" : "=f"(r) : "f"(x));
    return r;
}
// ---- packed f32x2 (Blackwell): two IEEE fp32 FMAs per issue, bit-identical --
__device__ __forceinline__ unsigned long long pk2b(float v) {  // broadcast
    unsigned long long r;
    asm("mov.b64 %0, {%1, %1};" : "=l"(r) : "r"(__float_as_uint(v)));
    return r;
}
__device__ __forceinline__ void fma2(unsigned long long &d,
                                     unsigned long long a, unsigned long long b) {
    asm("fma.rn.f32x2 %0, %1, %2, %0;" : "+l"(d) : "l"(a), "l"(b));
}
__device__ __forceinline__ void upk2(unsigned long long v, float &lo, float &hi) {
    unsigned int a, b;
    asm("mov.b64 {%0, %1}, %2;" : "=r"(a), "=r"(b) : "l"(v));
    lo = __uint_as_float(a);
    hi = __uint_as_float(b);
}
// pack (a,b) -> bf16x2 hi-plane + residual lo-plane (lo 16 bits = a)
__device__ __forceinline__ void split2(float a, float b, uint32_t& hi, uint32_t& lo) {
    uint32_t h;
    asm("cvt.rn.bf16x2.f32 %0, %1, %2;" : "=r"(h) : "f"(b), "f"(a));
    float ah = __uint_as_float(h << 16);
    float bh = __uint_as_float(h & 0xffff0000u);
    float al = a - ah, bl = b - bh;
    uint32_t l;
    asm("cvt.rn.bf16x2.f32 %0, %1, %2;" : "=r"(l) : "f"(bl), "f"(al));
    hi = h; lo = l;
}
__device__ __forceinline__ uint32_t pack_bf16x2(float a, float b) {
    uint32_t h;
    asm("cvt.rn.bf16x2.f32 %0, %1, %2;" : "=r"(h) : "f"(b), "f"(a));
    return h;
}

// shared inner GEMM: acc[4][4] += xs-tile^T(rows 4*ty..) x ws-tile(cols 4*tx..)
// rows paired into f32x2 lanes; a-pairs load pre-packed from smem.
__device__ __forceinline__ void gemm16_f32x2(
    unsigned long long acc2[2][4], const float* xs, const float* ws,
    int ty, int tx)
{
    #pragma unroll 4
    for (int c = 0; c < 64; c++) {
        ulonglong2 a2 = *(const ulonglong2*)&xs[c*68 + 4*ty];   // (a0,a1),(a2,a3)
        float4 w4 = *(const float4*)&ws[c*68 + 4*tx];
        unsigned long long w0 = pk2b(w4.x), w1 = pk2b(w4.y);
        unsigned long long w2 = pk2b(w4.z), w3 = pk2b(w4.w);
        fma2(acc2[0][0], a2.x, w0); fma2(acc2[1][0], a2.y, w0);
        fma2(acc2[0][1], a2.x, w1); fma2(acc2[1][1], a2.y, w1);
        fma2(acc2[0][2], a2.x, w2); fma2(acc2[1][2], a2.y, w2);
        fma2(acc2[0][3], a2.x, w3); fma2(acc2[1][3], a2.y, w3);
    }
}

// ---------------- kernel 1: projections -> bf16 hi/lo planes ----------------
__global__ __launch_bounds__(256) void proj3_kernel(
    const float* __restrict__ x,
    const float* __restrict__ wt, const float* __restrict__ bt,
    const float* __restrict__ wp, const float* __restrict__ bp,
    const float* __restrict__ wg, const float* __restrict__ bg)
{
    __shared__ __align__(16) float xs[64*68];
    __shared__ __align__(16) float ws[64*68];
    const int b  = blockIdx.y;
    const int n0 = blockIdx.x * 64;
    const int t  = threadIdx.x;
    const int tx = t & 15, ty = t >> 4;

    if (blockIdx.x == 0 && b == 0 && t < 128) g_stats[t] = 0.f;

    for (int i = t; i < 4096; i += 256) {
        int c = i >> 6, n = i & 63;
        xs[c*68 + n] = x[((size_t)b*64 + c)*6400 + n0 + n];
    }
    const float* W[3]  = {wt, wp, wg};
    const float* BV[3] = {bt, bp, bg};

    for (int m = 0; m < 3; m++) {
        __syncthreads();
        for (int i = t; i < 4096; i += 256) ws[(i & 63)*68 + (i >> 6)] = W[m][i];
        __syncthreads();

        unsigned long long acc2[2][4];
        #pragma unroll
        for (int j = 0; j < 4; j++) {
            unsigned long long bb = pk2b(BV[m][4*tx + j]);
            acc2[0][j] = bb; acc2[1][j] = bb;
        }
        gemm16_f32x2(acc2, xs, ws, ty, tx);

        float acc[4][4];
        #pragma unroll
        for (int j = 0; j < 4; j++) {
            upk2(acc2[0][j], acc[0][j], acc[1][j]);
            upk2(acc2[1][j], acc[2][j], acc[3][j]);
        }
        if (m == 0) {    // theta: pre-scale by log2(e) so softmax uses ex2 directly
            #pragma unroll
            for (int r = 0; r < 4; r++)
                #pragma unroll
                for (int j = 0; j < 4; j++) acc[r][j] *= LOG2E;
        }
        if (m < 2) {
            __nv_bfloat16* ph = (m == 0) ? g_q_h : g_k_h;
            __nv_bfloat16* pl = (m == 0) ? g_q_l : g_k_l;
            #pragma unroll
            for (int r = 0; r < 4; r++) {
                uint32_t h01, l01, h23, l23;
                split2(acc[r][0], acc[r][1], h01, l01);
                split2(acc[r][2], acc[r][3], h23, l23);
                size_t idx = ((size_t)b*6400 + n0 + 4*ty + r)*64 + 4*tx;
                *(uint2*)&ph[idx] = make_uint2(h01, h23);
                *(uint2*)&pl[idx] = make_uint2(l01, l23);
            }
        } else {
            #pragma unroll
            for (int j = 0; j < 4; j++) {
                uint32_t hA, lA, hB, lB;
                split2(acc[0][j], acc[1][j], hA, lA);
                split2(acc[2][j], acc[3][j], hB, lB);
                size_t idx = ((size_t)b*64 + 4*tx + j)*6400 + n0 + 4*ty;
                *(uint2*)&g_v_h[idx] = make_uint2(hA, hB);
                *(uint2*)&g_v_l[idx] = make_uint2(lA, lB);
            }
        }
    }
}

// ---------------- kernel 2: flash attention, split-K(3), V ping-pong --------
// smem: PQ (Q; V-odd after chunk 0) 0..16K, PK 16K..32K, PV (V-even) 32K..48K
#define PQH 0u
#define PQL 8192u
#define PKH 16384u
#define PKL 24576u
#define PVH 32768u
#define PVL 40960u

__device__ __forceinline__ void ld_plane(uint32_t dst, const __nv_bfloat16* src,
                                         int rowstride, int t)
{
    #pragma unroll
    for (int k = 0; k < 4; k++) {
        int idx = t + k*128;               // 512 chunks total
        int row = idx >> 3, ch = idx & 7;
        cpa16(dst + (uint32_t)row*128u + (uint32_t)((ch ^ (row & 7))*16),
              src + (size_t)row*rowstride + ch*8);
    }
}

__global__ __launch_bounds__(128, 4) void flash_kernel()
{
    __shared__ __align__(128) char smem[49152];
    const uint32_t sb = smem_u32(smem);
    const int t    = threadIdx.x;
    const int lane = t & 31;
    const int wid  = t >> 5;
    const int b    = blockIdx.y;
    const int n0   = blockIdx.x * 64;
    const int sp   = blockIdx.z;                      // key-range split: 0,1,2
    const int coff = (sp == 0) ? 0 : (sp == 1) ? 34 : 67;   // chunk offset
    const int nch  = (sp == 0) ? 34 : 33;                    // chunks this split
    const int kbase = coff * 64;
    const int m0   = wid * 16;

    // prologue: ONE group = {Q, K0, V0}
    ld_plane(sb + PQH, g_q_h + ((size_t)b*6400 + n0)*64, 64, t);
    ld_plane(sb + PQL, g_q_l + ((size_t)b*6400 + n0)*64, 64, t);
    ld_plane(sb + PKH, g_k_h + ((size_t)b*6400 + kbase)*64, 64, t);
    ld_plane(sb + PKL, g_k_l + ((size_t)b*6400 + kbase)*64, 64, t);
    ld_plane(sb + PVH, g_v_h + (size_t)b*64*6400 + kbase, 6400, t);
    ld_plane(sb + PVL, g_v_l + (size_t)b*64*6400 + kbase, 6400, t);
    asm volatile("cp.async.commit_group;" ::: "memory");

    // lane-derived ldmatrix address components
    const uint32_t ar   = (uint32_t)(lane & 7) + ((uint32_t)((lane >> 3) & 1) << 3);
    const uint32_t ax   = (uint32_t)((lane >> 4) & 1);
    const uint32_t axr  = (uint32_t)(lane & 7);
    const uint32_t br   = (uint32_t)(lane & 7);
    const uint32_t bx   = (uint32_t)((lane >> 3) & 1);
    const uint32_t bpl  = ((uint32_t)(lane >> 4) & 1) * 8192u;  // lanes 16-31 -> lo plane

    uint32_t qh[4][4], ql[4][4];
    float O[8][4];
    #pragma unroll
    for (int i = 0; i < 8; i++)
        #pragma unroll
        for (int j = 0; j < 4; j++) O[i][j] = 0.f;
    float lsA = 0.f, lsB = 0.f;

    #pragma unroll 1
    for (int i = 0; i < nch; i++) {
        // K(i) and V(i) landed (single group per chunk)
        asm volatile("cp.async.wait_group 0;" ::: "memory");
        __syncthreads();

        if (i == 0) {
            #pragma unroll
            for (int kb = 0; kb < 4; kb++) {
                uint32_t R  = (uint32_t)m0 + ar;
                uint32_t ch = ((uint32_t)(kb*2) + ax) ^ axr;
                ldmx4(qh[kb], sb + PQH + R*128u + ch*16u);
                ldmx4(ql[kb], sb + PQL + R*128u + ch*16u);
            }
        }
        const uint32_t vbuf = sb + ((i & 1) ? PQH : PVH);   // V(i) location

        // ---- S = Q K^T : 3-term split, fused hi/lo B-frag loads ----
        float S[8][4];
        #pragma unroll
        for (int nt = 0; nt < 8; nt++)
            #pragma unroll
            for (int j = 0; j < 4; j++) S[nt][j] = 0.f;

        #pragma unroll
        for (int kb = 0; kb < 4; kb++) {
            uint32_t kf[8][4];
            #pragma unroll
            for (int nt = 0; nt < 8; nt++) {
                uint32_t R  = (uint32_t)(nt*8) + br;
                uint32_t ch = ((uint32_t)(kb*2) + bx) ^ br;
                ldmx4(kf[nt], sb + PKH + bpl + R*128u + ch*16u);
            }
            #pragma unroll
            for (int nt = 0; nt < 8; nt++) mma_bf16(S[nt], qh[kb], &kf[nt][0]);
            #pragma unroll
            for (int nt = 0; nt < 8; nt++) mma_bf16(S[nt], qh[kb], &kf[nt][2]);
            #pragma unroll
            for (int nt = 0; nt < 8; nt++) mma_bf16(S[nt], ql[kb], &kf[nt][0]);
        }

        __syncthreads();       // K readers done (i==0: Q-frag readers done too)
        if (i < nch - 1) {     // prefetch K(i+1) and V(i+1) over softmax+PV
            ld_plane(sb + PKH, g_k_h + ((size_t)b*6400 + kbase + (i+1)*64)*64, 64, t);
            ld_plane(sb + PKL, g_k_l + ((size_t)b*6400 + kbase + (i+1)*64)*64, 64, t);
            uint32_t nv = sb + (((i + 1) & 1) ? PQH : PVH);
            ld_plane(nv,         g_v_h + (size_t)b*64*6400 + kbase + (i+1)*64, 6400, t);
            ld_plane(nv + 8192u, g_v_l + (size_t)b*64*6400 + kbase + (i+1)*64, 6400, t);
            asm volatile("cp.async.commit_group;" ::: "memory");
        }

        // ---- softmax numerator: exp2 (theta pre-scaled), hi-only P pack ----
        uint32_t ph[4][4];
        #pragma unroll
        for (int nt = 0; nt < 8; nt++) {
            float p0 = ex2(S[nt][0]);
            float p1 = ex2(S[nt][1]);
            float p2 = ex2(S[nt][2]);
            float p3 = ex2(S[nt][3]);
            lsA += p0 + p1;
            lsB += p2 + p3;
            int kb = nt >> 1, hf = (nt & 1) * 2;
            ph[kb][hf + 0] = pack_bf16x2(p0, p1);
            ph[kb][hf + 1] = pack_bf16x2(p2, p3);
        }

        // ---- O += P V : 2-term (Ph*Vh + Ph*Vl); no trailing sync needed ----
        #pragma unroll
        for (int kb = 0; kb < 4; kb++) {
            uint32_t vf[8][4];
            #pragma unroll
            for (int ct = 0; ct < 8; ct++) {
                uint32_t R  = (uint32_t)(ct*8) + br;
                uint32_t ch = ((uint32_t)(kb*2) + bx) ^ br;
                ldmx4(vf[ct], vbuf + bpl + R*128u + ch*16u);
            }
            #pragma unroll
            for (int ct = 0; ct < 8; ct++) mma_bf16(O[ct], ph[kb], &vf[ct][0]);
            #pragma unroll
            for (int ct = 0; ct < 8; ct++) mma_bf16(O[ct], ph[kb], &vf[ct][2]);
        }
    }

    // ---- epilogue: write UNNORMALIZED partial O and partial row sums l ----
    lsA += __shfl_xor_sync(0xffffffffu, lsA, 1);
    lsA += __shfl_xor_sync(0xffffffffu, lsA, 2);
    lsB += __shfl_xor_sync(0xffffffffu, lsB, 1);
    lsB += __shfl_xor_sync(0xffffffffu, lsB, 2);

    const int gq = lane >> 2, tq = lane & 3;
    if (tq == 0) {
        g_l[sp][(size_t)b*6400 + n0 + m0 + gq    ] = lsA;
        g_l[sp][(size_t)b*6400 + n0 + m0 + gq + 8] = lsB;
    }

    __syncthreads();
    float* stg = (float*)(smem + PKH);      // 64x64 f32 staging = 16KB (K region)
    #pragma unroll
    for (int ct = 0; ct < 8; ct++) {
        int c = ct*8 + 2*tq;
        stg[(c    )*64 + m0 + gq    ] = O[ct][0];
        stg[(c + 1)*64 + m0 + gq    ] = O[ct][1];
        stg[(c    )*64 + m0 + gq + 8] = O[ct][2];
        stg[(c + 1)*64 + m0 + gq + 8] = O[ct][3];
    }
    __syncthreads();
    for (int idx = t; idx < 1024; idx += 128) {
        int c = idx >> 4, chn = idx & 15;
        float4 v = *(float4*)&stg[c*64 + chn*4];
        *(float4*)&g_p[sp][((size_t)b*64 + c)*6400 + n0 + chn*4] = v;
    }
}

// ---------------- kernel 3: combine splits + W-conv + BN statistics ----------
__global__ __launch_bounds__(256) void convW_kernel(
    const float* __restrict__ wW, const float* __restrict__ bW)
{
    __shared__ __align__(16) float ys[64*68];
    __shared__ __align__(16) float ws[64*68];
    __shared__ float ssum[64], ssq[64], linv[64];
    const int b  = blockIdx.y;
    const int n0 = blockIdx.x * 64;
    const int t  = threadIdx.x;
    const int tx = t & 15, ty = t >> 4;

    if (t < 64) {
        size_t li = (size_t)b*6400 + n0 + t;
        linv[t] = 1.f / (g_l[0][li] + g_l[1][li] + g_l[2][li]);
        ssum[t] = 0.f; ssq[t] = 0.f;
    }
    __syncthreads();

    const float* p0 = g_p[0] + (size_t)b*64*6400;
    const float* p1 = g_p[1] + (size_t)b*64*6400;
    const float* p2 = g_p[2] + (size_t)b*64*6400;
    for (int i = t; i < 4096; i += 256) {
        int c = i >> 6, n = i & 63;
        size_t idx = (size_t)c*6400 + n0 + n;
        ys[c*68 + n] = (p0[idx] + p1[idx] + p2[idx]) * linv[n];
    }
    for (int i = t; i < 4096; i += 256) ws[(i & 63)*68 + (i >> 6)] = wW[i];
    __syncthreads();

    unsigned long long acc2[2][4];
    #pragma unroll
    for (int j = 0; j < 4; j++) {
        unsigned long long bb = pk2b(bW[4*tx + j]);
        acc2[0][j] = bb; acc2[1][j] = bb;
    }
    gemm16_f32x2(acc2, ys, ws, ty, tx);

    float acc[4][4];
    #pragma unroll
    for (int j = 0; j < 4; j++) {
        upk2(acc2[0][j], acc[0][j], acc[1][j]);
        upk2(acc2[1][j], acc[2][j], acc[3][j]);
    }

    float* dst = g_Wy + (size_t)b*64*6400;
    #pragma unroll
    for (int j = 0; j < 4; j++) {
        float4 v = make_float4(acc[0][j], acc[1][j], acc[2][j], acc[3][j]);
        *(float4*)&dst[(4*tx + j)*6400 + n0 + 4*ty] = v;
    }
    #pragma unroll
    for (int j = 0; j < 4; j++) {
        float s = 0.f, q = 0.f;
        #pragma unroll
        for (int r = 0; r < 4; r++) { s += acc[r][j]; q += acc[r][j]*acc[r][j]; }
        atomicAdd(&ssum[4*tx + j], s);
        atomicAdd(&ssq [4*tx + j], q);
    }
    __syncthreads();
    if (t < 64) {
        atomicAdd(&g_stats[t],      ssum[t]);
        atomicAdd(&g_stats[64 + t], ssq[t]);
    }
}

// ---------------- kernel 4: BN scale/shift + apply + residual (fused) --------
__global__ __launch_bounds__(256) void out_kernel(const float* __restrict__ x,
                                                  const float* __restrict__ gamma,
                                                  const float* __restrict__ beta,
                                                  float* __restrict__ out)
{
    int i   = blockIdx.x * 256 + threadIdx.x;
    int idx = i * 4;
    int c   = (idx / 6400) & 63;
    const float invN = 1.f / (float)(B_ * N_);
    float mean = g_stats[c] * invN;
    float var  = g_stats[64 + c] * invN - mean*mean;
    float sc   = gamma[c] * rsqrtf(var + 1e-5f);
    float sh   = beta[c] - mean*sc;
    float4 wy = *(const float4*)&g_Wy[idx];
    float4 xv = *(const float4*)&x[idx];
    float4 o;
    o.x = wy.x*sc + sh + xv.x;
    o.y = wy.y*sc + sh + xv.y;
    o.z = wy.z*sc + sh + xv.z;
    o.w = wy.w*sc + sh + xv.w;
    *(float4*)&out[idx] = o;
}

// ---------------- launch -------------------------------------------------------
extern "C" void kernel_launch(void* const* d_in, const int* in_sizes, int n_in,
                              void* d_out, int out_size)
{
    const float* x     = (const float*)d_in[0];
    const float* wt    = (const float*)d_in[1];
    const float* bt    = (const float*)d_in[2];
    const float* wp    = (const float*)d_in[3];
    const float* bp    = (const float*)d_in[4];
    const float* wg    = (const float*)d_in[5];
    const float* bg    = (const float*)d_in[6];
    const float* wW    = (const float*)d_in[7];
    const float* bW    = (const float*)d_in[8];
    const float* gamma = (const float*)d_in[9];
    const float* beta  = (const float*)d_in[10];

    dim3 gproj(100, B_);
    proj3_kernel <<<gproj, 256>>>(x, wt, bt, wp, bp, wg, bg);
    dim3 gflash(100, B_, 3);               // 1200 CTAs: q-tile x batch x key-split
    flash_kernel <<<gflash, 128>>>();
    convW_kernel <<<gproj, 256>>>(wW, bW);
    out_kernel   <<<(B_*C_*N_)/4/256, 256>>>(x, gamma, beta, (float*)d_out);
}

// round 15
// speedup vs baseline: 1.1665x; 1.0153x over previous
#include <cuda_runtime.h>
#include <cuda_bf16.h>
#include <cstdint>

#define B_ 4
#define C_ 64
#define N_ 6400
#define LOG2E 1.4426950408889634f

// ---------------- device-global scratch -------------------------------------
__device__ __align__(16) __nv_bfloat16 g_q_h[B_*N_*C_];   // [B][N][C] (theta, pre-scaled by log2e)
__device__ __align__(16) __nv_bfloat16 g_q_l[B_*N_*C_];
__device__ __align__(16) __nv_bfloat16 g_k_h[B_*N_*C_];   // [B][N][C]
__device__ __align__(16) __nv_bfloat16 g_k_l[B_*N_*C_];
__device__ __align__(16) __nv_bfloat16 g_v_h[B_*C_*N_];   // [B][C][N]
__device__ __align__(16) __nv_bfloat16 g_v_l[B_*C_*N_];
__device__ __align__(16) float g_p[3][B_*C_*N_];          // per-split partial O (unnormalized)
__device__ float g_l[3][B_*N_];                            // per-split partial row sums
__device__ float g_Wy  [B_*C_*N_];
__device__ float g_stats[2*C_];

// ---------------- helpers ----------------------------------------------------
__device__ __forceinline__ uint32_t smem_u32(const void* p) {
    uint32_t a;
    asm("{ .reg .u64 t; cvta.to.shared.u64 t, %1; cvt.u32.u64 %0, t; }" : "=r"(a) : "l"(p));
    return a;
}
__device__ __forceinline__ void cpa16(uint32_t dst, const void* src) {
    asm volatile("cp.async.cg.shared.global [%0], [%1], 16;" :: "r"(dst), "l"(src));
}
__device__ __forceinline__ void mma_bf16(float* d, const uint32_t* a, const uint32_t* b) {
    asm volatile("mma.sync.aligned.m16n8k16.row.col.f32.bf16.bf16.f32 "
        "{%0,%1,%2,%3}, {%4,%5,%6,%7}, {%8,%9}, {%0,%1,%2,%3};"
        : "+f"(d[0]), "+f"(d[1]), "+f"(d[2]), "+f"(d[3])
        : "r"(a[0]), "r"(a[1]), "r"(a[2]), "r"(a[3]), "r"(b[0]), "r"(b[1]));
}
__device__ __forceinline__ void ldmx4(uint32_t* r, uint32_t a) {
    asm volatile("ldmatrix.sync.aligned.m8n8.x4.shared.b16 {%0,%1,%2,%3}, [%4];"
        : "=r"(r[0]), "=r"(r[1]), "=r"(r[2]), "=r"(r[3]) : "r"(a));
}
__device__ __forceinline__ float ex2(float x) {
    float r;
    asm("ex2.approx.f32 %0, %1;" : "=f"(r) : "f"(x));
    return r;
}
// ---- packed f32x2 (Blackwell): two IEEE fp32 FMAs per issue, bit-identical --
__device__ __forceinline__ unsigned long long pk2b(float v) {  // broadcast
    unsigned long long r;
    asm("mov.b64 %0, {%1, %1};" : "=l"(r) : "r"(__float_as_uint(v)));
    return r;
}
__device__ __forceinline__ void fma2(unsigned long long &d,
                                     unsigned long long a, unsigned long long b) {
    asm("fma.rn.f32x2 %0, %1, %2, %0;" : "+l"(d) : "l"(a), "l"(b));
}
__device__ __forceinline__ void upk2(unsigned long long v, float &lo, float &hi) {
    unsigned int a, b;
    asm("mov.b64 {%0, %1}, %2;" : "=r"(a), "=r"(b) : "l"(v));
    lo = __uint_as_float(a);
    hi = __uint_as_float(b);
}
// pack (a,b) -> bf16x2 hi-plane + residual lo-plane (lo 16 bits = a)
__device__ __forceinline__ void split2(float a, float b, uint32_t& hi, uint32_t& lo) {
    uint32_t h;
    asm("cvt.rn.bf16x2.f32 %0, %1, %2;" : "=r"(h) : "f"(b), "f"(a));
    float ah = __uint_as_float(h << 16);
    float bh = __uint_as_float(h & 0xffff0000u);
    float al = a - ah, bl = b - bh;
    uint32_t l;
    asm("cvt.rn.bf16x2.f32 %0, %1, %2;" : "=r"(l) : "f"(bl), "f"(al));
    hi = h; lo = l;
}
__device__ __forceinline__ uint32_t pack_bf16x2(float a, float b) {
    uint32_t h;
    asm("cvt.rn.bf16x2.f32 %0, %1, %2;" : "=r"(h) : "f"(b), "f"(a));
    return h;
}

// shared inner GEMM: acc += xs-tile^T(rows 4*ty..) x ws-tile(cols 4*tx..)
// rows paired into f32x2 lanes; a-pairs load pre-packed from smem.
__device__ __forceinline__ void gemm16_f32x2(
    unsigned long long acc2[2][4], const float* xs, const float* ws,
    int ty, int tx)
{
    #pragma unroll 4
    for (int c = 0; c < 64; c++) {
        ulonglong2 a2 = *(const ulonglong2*)&xs[c*68 + 4*ty];   // (a0,a1),(a2,a3)
        float4 w4 = *(const float4*)&ws[c*68 + 4*tx];
        unsigned long long w0 = pk2b(w4.x), w1 = pk2b(w4.y);
        unsigned long long w2 = pk2b(w4.z), w3 = pk2b(w4.w);
        fma2(acc2[0][0], a2.x, w0); fma2(acc2[1][0], a2.y, w0);
        fma2(acc2[0][1], a2.x, w1); fma2(acc2[1][1], a2.y, w1);
        fma2(acc2[0][2], a2.x, w2); fma2(acc2[1][2], a2.y, w2);
        fma2(acc2[0][3], a2.x, w3); fma2(acc2[1][3], a2.y, w3);
    }
}

// ---------------- kernel 1: projections -> bf16 hi/lo planes ----------------
__global__ __launch_bounds__(256) void proj3_kernel(
    const float* __restrict__ x,
    const float* __restrict__ wt, const float* __restrict__ bt,
    const float* __restrict__ wp, const float* __restrict__ bp,
    const float* __restrict__ wg, const float* __restrict__ bg)
{
    __shared__ __align__(16) float xs[64*68];
    __shared__ __align__(16) float ws[64*68];
    const int b  = blockIdx.y;
    const int n0 = blockIdx.x * 64;
    const int t  = threadIdx.x;
    const int tx = t & 15, ty = t >> 4;

    if (blockIdx.x == 0 && b == 0 && t < 128) g_stats[t] = 0.f;

    // vectorized x tile load: 1024 float4 chunks
    for (int i = t; i < 1024; i += 256) {
        int c = i >> 4, n4 = i & 15;
        float4 v = *(const float4*)&x[((size_t)b*64 + c)*6400 + n0 + n4*4];
        *(float4*)&xs[c*68 + n4*4] = v;
    }
    const float* W[3]  = {wt, wp, wg};
    const float* BV[3] = {bt, bp, bg};

    for (int m = 0; m < 3; m++) {
        __syncthreads();
        // vectorized weight load (float4 over c), scalar transpose stores
        for (int i = t; i < 1024; i += 256) {
            int o = i >> 4, c4 = (i & 15) * 4;
            float4 v = *(const float4*)&W[m][o*64 + c4];
            ws[(c4    )*68 + o] = v.x;
            ws[(c4 + 1)*68 + o] = v.y;
            ws[(c4 + 2)*68 + o] = v.z;
            ws[(c4 + 3)*68 + o] = v.w;
        }
        __syncthreads();

        unsigned long long acc2[2][4];
        #pragma unroll
        for (int j = 0; j < 4; j++) {
            unsigned long long bb = pk2b(BV[m][4*tx + j]);
            acc2[0][j] = bb; acc2[1][j] = bb;
        }
        gemm16_f32x2(acc2, xs, ws, ty, tx);

        float acc[4][4];
        #pragma unroll
        for (int j = 0; j < 4; j++) {
            upk2(acc2[0][j], acc[0][j], acc[1][j]);
            upk2(acc2[1][j], acc[2][j], acc[3][j]);
        }
        if (m == 0) {    // theta: pre-scale by log2(e) so softmax uses ex2 directly
            #pragma unroll
            for (int r = 0; r < 4; r++)
                #pragma unroll
                for (int j = 0; j < 4; j++) acc[r][j] *= LOG2E;
        }
        if (m < 2) {
            __nv_bfloat16* ph = (m == 0) ? g_q_h : g_k_h;
            __nv_bfloat16* pl = (m == 0) ? g_q_l : g_k_l;
            #pragma unroll
            for (int r = 0; r < 4; r++) {
                uint32_t h01, l01, h23, l23;
                split2(acc[r][0], acc[r][1], h01, l01);
                split2(acc[r][2], acc[r][3], h23, l23);
                size_t idx = ((size_t)b*6400 + n0 + 4*ty + r)*64 + 4*tx;
                *(uint2*)&ph[idx] = make_uint2(h01, h23);
                *(uint2*)&pl[idx] = make_uint2(l01, l23);
            }
        } else {
            #pragma unroll
            for (int j = 0; j < 4; j++) {
                uint32_t hA, lA, hB, lB;
                split2(acc[0][j], acc[1][j], hA, lA);
                split2(acc[2][j], acc[3][j], hB, lB);
                size_t idx = ((size_t)b*64 + 4*tx + j)*6400 + n0 + 4*ty;
                *(uint2*)&g_v_h[idx] = make_uint2(hA, hB);
                *(uint2*)&g_v_l[idx] = make_uint2(lA, lB);
            }
        }
    }
}

// ---------------- kernel 2: flash attention, split-K(3), V ping-pong --------
// smem: PQ (Q; V-odd after chunk 0) 0..16K, PK 16K..32K, PV (V-even) 32K..48K
#define PQH 0u
#define PQL 8192u
#define PKH 16384u
#define PKL 24576u
#define PVH 32768u
#define PVL 40960u

__device__ __forceinline__ void ld_plane(uint32_t dst, const __nv_bfloat16* src,
                                         int rowstride, int t)
{
    #pragma unroll
    for (int k = 0; k < 4; k++) {
        int idx = t + k*128;               // 512 chunks total
        int row = idx >> 3, ch = idx & 7;
        cpa16(dst + (uint32_t)row*128u + (uint32_t)((ch ^ (row & 7))*16),
              src + (size_t)row*rowstride + ch*8);
    }
}

__global__ __launch_bounds__(128, 4) void flash_kernel()
{
    __shared__ __align__(128) char smem[49152];
    const uint32_t sb = smem_u32(smem);
    const int t    = threadIdx.x;
    const int lane = t & 31;
    const int wid  = t >> 5;
    const int b    = blockIdx.y;
    const int n0   = blockIdx.x * 64;
    const int sp   = blockIdx.z;                      // key-range split: 0,1,2
    const int coff = (sp == 0) ? 0 : (sp == 1) ? 34 : 67;   // chunk offset
    const int nch  = (sp == 0) ? 34 : 33;                    // chunks this split
    const int kbase = coff * 64;
    const int m0   = wid * 16;

    // prologue: ONE group = {Q, K0, V0}
    ld_plane(sb + PQH, g_q_h + ((size_t)b*6400 + n0)*64, 64, t);
    ld_plane(sb + PQL, g_q_l + ((size_t)b*6400 + n0)*64, 64, t);
    ld_plane(sb + PKH, g_k_h + ((size_t)b*6400 + kbase)*64, 64, t);
    ld_plane(sb + PKL, g_k_l + ((size_t)b*6400 + kbase)*64, 64, t);
    ld_plane(sb + PVH, g_v_h + (size_t)b*64*6400 + kbase, 6400, t);
    ld_plane(sb + PVL, g_v_l + (size_t)b*64*6400 + kbase, 6400, t);
    asm volatile("cp.async.commit_group;" ::: "memory");

    // lane-derived ldmatrix address components
    const uint32_t ar   = (uint32_t)(lane & 7) + ((uint32_t)((lane >> 3) & 1) << 3);
    const uint32_t ax   = (uint32_t)((lane >> 4) & 1);
    const uint32_t axr  = (uint32_t)(lane & 7);
    const uint32_t br   = (uint32_t)(lane & 7);
    const uint32_t bx   = (uint32_t)((lane >> 3) & 1);
    const uint32_t bpl  = ((uint32_t)(lane >> 4) & 1) * 8192u;  // lanes 16-31 -> lo plane

    uint32_t qh[4][4], ql[4][4];
    float O[8][4];
    #pragma unroll
    for (int i = 0; i < 8; i++)
        #pragma unroll
        for (int j = 0; j < 4; j++) O[i][j] = 0.f;
    float lsA = 0.f, lsB = 0.f;

    #pragma unroll 1
    for (int i = 0; i < nch; i++) {
        // K(i) and V(i) landed (single group per chunk)
        asm volatile("cp.async.wait_group 0;" ::: "memory");
        __syncthreads();

        if (i == 0) {
            #pragma unroll
            for (int kb = 0; kb < 4; kb++) {
                uint32_t R  = (uint32_t)m0 + ar;
                uint32_t ch = ((uint32_t)(kb*2) + ax) ^ axr;
                ldmx4(qh[kb], sb + PQH + R*128u + ch*16u);
                ldmx4(ql[kb], sb + PQL + R*128u + ch*16u);
            }
        }
        const uint32_t vbuf = sb + ((i & 1) ? PQH : PVH);   // V(i) location

        // ---- S = Q K^T : 3-term split, fused hi/lo B-frag loads ----
        float S[8][4];
        #pragma unroll
        for (int nt = 0; nt < 8; nt++)
            #pragma unroll
            for (int j = 0; j < 4; j++) S[nt][j] = 0.f;

        #pragma unroll
        for (int kb = 0; kb < 4; kb++) {
            uint32_t kf[8][4];
            #pragma unroll
            for (int nt = 0; nt < 8; nt++) {
                uint32_t R  = (uint32_t)(nt*8) + br;
                uint32_t ch = ((uint32_t)(kb*2) + bx) ^ br;
                ldmx4(kf[nt], sb + PKH + bpl + R*128u + ch*16u);
            }
            #pragma unroll
            for (int nt = 0; nt < 8; nt++) mma_bf16(S[nt], qh[kb], &kf[nt][0]);
            #pragma unroll
            for (int nt = 0; nt < 8; nt++) mma_bf16(S[nt], qh[kb], &kf[nt][2]);
            #pragma unroll
            for (int nt = 0; nt < 8; nt++) mma_bf16(S[nt], ql[kb], &kf[nt][0]);
        }

        __syncthreads();       // K readers done (i==0: Q-frag readers done too)
        if (i < nch - 1) {     // prefetch K(i+1) and V(i+1) over softmax+PV
            ld_plane(sb + PKH, g_k_h + ((size_t)b*6400 + kbase + (i+1)*64)*64, 64, t);
            ld_plane(sb + PKL, g_k_l + ((size_t)b*6400 + kbase + (i+1)*64)*64, 64, t);
            uint32_t nv = sb + (((i + 1) & 1) ? PQH : PVH);
            ld_plane(nv,         g_v_h + (size_t)b*64*6400 + kbase + (i+1)*64, 6400, t);
            ld_plane(nv + 8192u, g_v_l + (size_t)b*64*6400 + kbase + (i+1)*64, 6400, t);
            asm volatile("cp.async.commit_group;" ::: "memory");
        }

        // ---- softmax numerator: exp2 (theta pre-scaled), hi-only P pack ----
        uint32_t ph[4][4];
        #pragma unroll
        for (int nt = 0; nt < 8; nt++) {
            float p0 = ex2(S[nt][0]);
            float p1 = ex2(S[nt][1]);
            float p2 = ex2(S[nt][2]);
            float p3 = ex2(S[nt][3]);
            lsA += p0 + p1;
            lsB += p2 + p3;
            int kb = nt >> 1, hf = (nt & 1) * 2;
            ph[kb][hf + 0] = pack_bf16x2(p0, p1);
            ph[kb][hf + 1] = pack_bf16x2(p2, p3);
        }

        // ---- O += P V : 2-term (Ph*Vh + Ph*Vl); no trailing sync needed ----
        #pragma unroll
        for (int kb = 0; kb < 4; kb++) {
            uint32_t vf[8][4];
            #pragma unroll
            for (int ct = 0; ct < 8; ct++) {
                uint32_t R  = (uint32_t)(ct*8) + br;
                uint32_t ch = ((uint32_t)(kb*2) + bx) ^ br;
                ldmx4(vf[ct], vbuf + bpl + R*128u + ch*16u);
            }
            #pragma unroll
            for (int ct = 0; ct < 8; ct++) mma_bf16(O[ct], ph[kb], &vf[ct][0]);
            #pragma unroll
            for (int ct = 0; ct < 8; ct++) mma_bf16(O[ct], ph[kb], &vf[ct][2]);
        }
    }

    // ---- epilogue: write UNNORMALIZED partial O and partial row sums l ----
    lsA += __shfl_xor_sync(0xffffffffu, lsA, 1);
    lsA += __shfl_xor_sync(0xffffffffu, lsA, 2);
    lsB += __shfl_xor_sync(0xffffffffu, lsB, 1);
    lsB += __shfl_xor_sync(0xffffffffu, lsB, 2);

    const int gq = lane >> 2, tq = lane & 3;
    if (tq == 0) {
        g_l[sp][(size_t)b*6400 + n0 + m0 + gq    ] = lsA;
        g_l[sp][(size_t)b*6400 + n0 + m0 + gq + 8] = lsB;
    }

    __syncthreads();
    float* stg = (float*)(smem + PKH);      // 64x64 f32 staging = 16KB (K region)
    #pragma unroll
    for (int ct = 0; ct < 8; ct++) {
        int c = ct*8 + 2*tq;
        stg[(c    )*64 + m0 + gq    ] = O[ct][0];
        stg[(c + 1)*64 + m0 + gq    ] = O[ct][1];
        stg[(c    )*64 + m0 + gq + 8] = O[ct][2];
        stg[(c + 1)*64 + m0 + gq + 8] = O[ct][3];
    }
    __syncthreads();
    for (int idx = t; idx < 1024; idx += 128) {
        int c = idx >> 4, chn = idx & 15;
        float4 v = *(float4*)&stg[c*64 + chn*4];
        *(float4*)&g_p[sp][((size_t)b*64 + c)*6400 + n0 + chn*4] = v;
    }
}

// ---------------- kernel 3: combine splits + W-conv + BN statistics ----------
__global__ __launch_bounds__(256) void convW_kernel(
    const float* __restrict__ wW, const float* __restrict__ bW)
{
    __shared__ __align__(16) float ys[64*68];
    __shared__ __align__(16) float ws[64*68];
    __shared__ float ssum[64], ssq[64], linv[64];
    const int b  = blockIdx.y;
    const int n0 = blockIdx.x * 64;
    const int t  = threadIdx.x;
    const int tx = t & 15, ty = t >> 4;

    if (t < 64) {
        size_t li = (size_t)b*6400 + n0 + t;
        linv[t] = 1.f / (g_l[0][li] + g_l[1][li] + g_l[2][li]);
        ssum[t] = 0.f; ssq[t] = 0.f;
    }
    __syncthreads();

    const float* p0 = g_p[0] + (size_t)b*64*6400;
    const float* p1 = g_p[1] + (size_t)b*64*6400;
    const float* p2 = g_p[2] + (size_t)b*64*6400;
    // vectorized split combine: float4 over n
    for (int i = t; i < 1024; i += 256) {
        int c = i >> 4, n4 = (i & 15) * 4;
        size_t idx = (size_t)c*6400 + n0 + n4;
        float4 a = *(const float4*)&p0[idx];
        float4 bb = *(const float4*)&p1[idx];
        float4 cc = *(const float4*)&p2[idx];
        float4 r;
        r.x = (a.x + bb.x + cc.x) * linv[n4    ];
        r.y = (a.y + bb.y + cc.y) * linv[n4 + 1];
        r.z = (a.z + bb.z + cc.z) * linv[n4 + 2];
        r.w = (a.w + bb.w + cc.w) * linv[n4 + 3];
        *(float4*)&ys[c*68 + n4] = r;
    }
    for (int i = t; i < 1024; i += 256) {
        int o = i >> 4, c4 = (i & 15) * 4;
        float4 v = *(const float4*)&wW[o*64 + c4];
        ws[(c4    )*68 + o] = v.x;
        ws[(c4 + 1)*68 + o] = v.y;
        ws[(c4 + 2)*68 + o] = v.z;
        ws[(c4 + 3)*68 + o] = v.w;
    }
    __syncthreads();

    unsigned long long acc2[2][4];
    #pragma unroll
    for (int j = 0; j < 4; j++) {
        unsigned long long bb = pk2b(bW[4*tx + j]);
        acc2[0][j] = bb; acc2[1][j] = bb;
    }
    gemm16_f32x2(acc2, ys, ws, ty, tx);

    float acc[4][4];
    #pragma unroll
    for (int j = 0; j < 4; j++) {
        upk2(acc2[0][j], acc[0][j], acc[1][j]);
        upk2(acc2[1][j], acc[2][j], acc[3][j]);
    }

    float* dst = g_Wy + (size_t)b*64*6400;
    #pragma unroll
    for (int j = 0; j < 4; j++) {
        float4 v = make_float4(acc[0][j], acc[1][j], acc[2][j], acc[3][j]);
        *(float4*)&dst[(4*tx + j)*6400 + n0 + 4*ty] = v;
    }
    #pragma unroll
    for (int j = 0; j < 4; j++) {
        float s = 0.f, q = 0.f;
        #pragma unroll
        for (int r = 0; r < 4; r++) { s += acc[r][j]; q += acc[r][j]*acc[r][j]; }
        atomicAdd(&ssum[4*tx + j], s);
        atomicAdd(&ssq [4*tx + j], q);
    }
    __syncthreads();
    if (t < 64) {
        atomicAdd(&g_stats[t],      ssum[t]);
        atomicAdd(&g_stats[64 + t], ssq[t]);
    }
}

// ---------------- kernel 4: BN scale/shift + apply + residual (fused) --------
__global__ __launch_bounds__(256) void out_kernel(const float* __restrict__ x,
                                                  const float* __restrict__ gamma,
                                                  const float* __restrict__ beta,
                                                  float* __restrict__ out)
{
    const float invN = 1.f / (float)(B_ * N_);
    #pragma unroll
    for (int half = 0; half < 2; half++) {
        int i   = blockIdx.x * 256 + threadIdx.x + half * 204800;  // float4 index
        int idx = i * 4;
        int c   = (idx / 6400) & 63;
        float mean = g_stats[c] * invN;
        float var  = g_stats[64 + c] * invN - mean*mean;
        float sc   = gamma[c] * rsqrtf(var + 1e-5f);
        float sh   = beta[c] - mean*sc;
        float4 wy = *(const float4*)&g_Wy[idx];
        float4 xv = *(const float4*)&x[idx];
        float4 o;
        o.x = wy.x*sc + sh + xv.x;
        o.y = wy.y*sc + sh + xv.y;
        o.z = wy.z*sc + sh + xv.z;
        o.w = wy.w*sc + sh + xv.w;
        *(float4*)&out[idx] = o;
    }
}

// ---------------- launch -------------------------------------------------------
extern "C" void kernel_launch(void* const* d_in, const int* in_sizes, int n_in,
                              void* d_out, int out_size)
{
    const float* x     = (const float*)d_in[0];
    const float* wt    = (const float*)d_in[1];
    const float* bt    = (const float*)d_in[2];
    const float* wp    = (const float*)d_in[3];
    const float* bp    = (const float*)d_in[4];
    const float* wg    = (const float*)d_in[5];
    const float* bg    = (const float*)d_in[6];
    const float* wW    = (const float*)d_in[7];
    const float* bW    = (const float*)d_in[8];
    const float* gamma = (const float*)d_in[9];
    const float* beta  = (const float*)d_in[10];

    dim3 gproj(100, B_);
    proj3_kernel <<<gproj, 256>>>(x, wt, bt, wp, bp, wg, bg);
    dim3 gflash(100, B_, 3);               // 1200 CTAs: q-tile x batch x key-split
    flash_kernel <<<gflash, 128>>>();
    convW_kernel <<<gproj, 256>>>(wW, bW);
    out_kernel   <<<800, 256>>>(x, gamma, beta, (float*)d_out);
}